// round 12
// baseline (speedup 1.0000x reference)
#include <cuda_runtime.h>
#include <cstdint>
#include <math.h>

#define BATCH  4
#define SEQ    1024
#define DMODEL 512
#define DINNER 1024
#define DSTATE 32
#define DTRANK 32
#define DBC_W  96
#define NROWS  (BATCH*SEQ)   // 4096
#define XSPLIT 4

// ================= scratch =================
__device__ float g_xz    [BATCH*SEQ*2*DINNER];
__device__ float g_ut    [BATCH*DINNER*SEQ];
__device__ float g_zt    [BATCH*DINNER*SEQ];
__device__ float g_dbcp  [XSPLIT*BATCH*SEQ*DBC_W];
__device__ float g_dbc   [BATCH*SEQ*DBC_W];
__device__ float g_yt    [BATCH*DINNER*SEQ];
__device__ float g_y2    [BATCH*SEQ*DMODEL];
__device__ float g_yn    [BATCH*SEQ*DMODEL];

__device__ __forceinline__ int perm_src(int p) {
  int r = p >> 5, c = p & 31;
  if (r & 1) c = 31 - c;
  return (r << 5) | c;
}
__device__ __forceinline__ int remap_row(int m) {
  return (m & ~(SEQ - 1)) + perm_src(m & (SEQ - 1));
}
__device__ __forceinline__ float softplusf(float x) {
  return fmaxf(x, 0.f) + __logf(1.f + __expf(-fabsf(x)));
}
__device__ __forceinline__ float siluf(float x) {
  return __fdividef(x, 1.f + __expf(-x));
}
__device__ __forceinline__ float fast_erff(float x) {
  float ax = fabsf(x);
  float t = __frcp_rn(fmaf(0.3275911f, ax, 1.f));
  float p = t * fmaf(t, fmaf(t, fmaf(t, fmaf(t, 1.061405429f, -1.453152027f),
                     1.421413741f), -0.284496736f), 0.254829592f);
  float r = 1.f - p * __expf(-ax * ax);
  return copysignf(r, x);
}
__device__ __forceinline__ float geluf(float x) {
  return 0.5f * x * (1.f + fast_erff(x * 0.70710678118654752f));
}
__device__ __forceinline__ uint32_t smem_u32(const void* p) {
  uint32_t a;
  asm("{ .reg .u64 t; cvta.to.shared.u64 t, %1; cvt.u32.u64 %0, t; }" : "=r"(a) : "l"(p));
  return a;
}
__device__ __forceinline__ void cp16(void* dst, const void* src) {
  asm volatile("cp.async.cg.shared.global [%0], [%1], 16;"
               :: "r"(smem_u32(dst)), "l"(src));
}
__device__ __forceinline__ void cp16z(void* dst, const void* src, bool valid) {
  int sz = valid ? 16 : 0;
  asm volatile("cp.async.cg.shared.global [%0], [%1], 16, %2;"
               :: "r"(smem_u32(dst)), "l"(src), "r"(sz));
}
#define CP_COMMIT() asm volatile("cp.async.commit_group;" ::: "memory")
#define CP_WAIT1()  asm volatile("cp.async.wait_group 1;" ::: "memory")
#define CP_WAIT0()  asm volatile("cp.async.wait_group 0;" ::: "memory")

#define LDSM4(r0, r1, r2, r3, addr) \
  asm volatile("ldmatrix.sync.aligned.m8n8.x4.shared.b16 {%0,%1,%2,%3}, [%4];" \
    : "=r"(r0), "=r"(r1), "=r"(r2), "=r"(r3) : "r"(addr))

__device__ __forceinline__ void mma_tf32(float* c, const uint32_t* a, const uint32_t* b) {
  asm volatile(
    "mma.sync.aligned.m16n8k8.row.col.f32.tf32.tf32.f32 "
    "{%0,%1,%2,%3}, {%4,%5,%6,%7}, {%8,%9}, {%0,%1,%2,%3};"
    : "+f"(c[0]), "+f"(c[1]), "+f"(c[2]), "+f"(c[3])
    : "r"(a[0]), "r"(a[1]), "r"(a[2]), "r"(a[3]), "r"(b[0]), "r"(b[1]));
}

// ================= GEMM NT (templated MT, swizzled smem + ldmatrix, 3-stage) =====
template<int MT, int WMW>
__global__ __launch_bounds__(256, 2) void gemm_nt(const float* __restrict__ A,
    const float* __restrict__ B, float* __restrict__ C, int M, int N, int K,
    int gatherA, int epi, const float* __restrict__ bias,
    const float* __restrict__ resid) {
  constexpr int WNW = 8 / WMW;
  constexpr int WNT = 128 / WNW;
  constexpr int JF  = WNT / 8;
  constexpr int JF2 = JF / 2;
  constexpr int APASS = MT / 32;
  constexpr int STG = (MT + 128) * 32;
  extern __shared__ float sm[];
  const uint32_t sbase = smem_u32(sm);
  const int tid = threadIdx.x;
  const int wid = tid >> 5, lane = tid & 31;
  const int wm = wid % WMW, wn = wid / WMW;
  const int group = lane >> 2, tg = lane & 3;
  const int m0 = blockIdx.y * MT, n0 = blockIdx.x * 128;
  const int lr = tid >> 3, lk = tid & 7;
  const int KC = K / 32;

  int a_row[2], b_row[JF2];
#pragma unroll
  for (int i = 0; i < 2; i++)
    a_row[i] = wm * 32 + i * 16 + (lane & 7) + ((lane & 8) ? 8 : 0);
#pragma unroll
  for (int j2 = 0; j2 < JF2; j2++)
    b_row[j2] = wn * WNT + j2 * 16 + (lane & 7) + ((lane & 16) ? 8 : 0);
  const int a_qc = (lane & 16) ? 1 : 0;
  const int b_qc = (lane & 8) ? 1 : 0;

  float acc[2][JF][4] = {};

  int arow[APASS];
#pragma unroll
  for (int pass = 0; pass < APASS; ++pass) {
    int m = m0 + lr + pass * 32;
    arow[pass] = gatherA ? remap_row(m) : m;
  }

#define NT_LOAD(c) do { \
    int k0 = (c) * 32; \
    float* st = sm + ((c) % 3) * STG; \
    _Pragma("unroll") \
    for (int pass = 0; pass < APASS; ++pass) { \
      int r = lr + pass * 32; \
      int sc = (lk ^ (r & 7)) * 4; \
      cp16(st + r * 32 + sc, &A[(size_t)arow[pass] * K + k0 + lk * 4]); \
    } \
    _Pragma("unroll") \
    for (int pass = 0; pass < 4; ++pass) { \
      int r = lr + pass * 32; \
      int sc = (lk ^ (r & 7)) * 4; \
      cp16(st + MT * 32 + r * 32 + sc, &B[(size_t)(n0 + r) * K + k0 + lk * 4]); \
    } \
    CP_COMMIT(); \
  } while (0)

  NT_LOAD(0);
  if (KC > 1) NT_LOAD(1);
  for (int c = 0; c < KC; ++c) {
    if (c + 1 < KC) CP_WAIT1(); else CP_WAIT0();
    __syncthreads();
    if (c + 2 < KC) NT_LOAD(c + 2);
    const uint32_t stA = sbase + ((c % 3) * STG) * 4;
    const uint32_t stB = stA + MT * 32 * 4;
#pragma unroll
    for (int ks = 0; ks < 4; ++ks) {
      uint32_t af[2][4], bfr[JF][2];
#pragma unroll
      for (int i = 0; i < 2; i++) {
        uint32_t ad = stA + a_row[i] * 128 + ((((2 * ks + a_qc) ^ (a_row[i] & 7))) << 4);
        LDSM4(af[i][0], af[i][1], af[i][2], af[i][3], ad);
      }
#pragma unroll
      for (int j2 = 0; j2 < JF2; j2++) {
        uint32_t bd = stB + b_row[j2] * 128 + ((((2 * ks + b_qc) ^ (b_row[j2] & 7))) << 4);
        uint32_t r0, r1, r2, r3;
        LDSM4(r0, r1, r2, r3, bd);
        bfr[2*j2][0] = r0; bfr[2*j2][1] = r1;
        bfr[2*j2+1][0] = r2; bfr[2*j2+1][1] = r3;
      }
#pragma unroll
      for (int i = 0; i < 2; i++)
#pragma unroll
        for (int j = 0; j < JF; j++)
          mma_tf32(acc[i][j], af[i], bfr[j]);
    }
  }
#undef NT_LOAD
  if (epi == 0) {
#pragma unroll
    for (int i = 0; i < 2; i++) {
      int row0 = m0 + wm * 32 + i * 16 + group;
#pragma unroll
      for (int j = 0; j < JF; j++) {
        int col = n0 + wn * WNT + j * 8 + tg * 2;
        *(float2*)&C[(size_t)row0 * N + col]       = make_float2(acc[i][j][0], acc[i][j][1]);
        *(float2*)&C[(size_t)(row0 + 8) * N + col] = make_float2(acc[i][j][2], acc[i][j][3]);
      }
    }
  } else {
#pragma unroll
    for (int i = 0; i < 2; i++) {
      int row0 = m0 + wm * 32 + i * 16 + group;
      int ra = remap_row(row0), rb = remap_row(row0 + 8);
#pragma unroll
      for (int j = 0; j < JF; j++) {
        int col = n0 + wn * WNT + j * 8 + tg * 2;
        float b0 = bias[col], b1 = bias[col + 1];
        size_t oa = (size_t)ra * N + col, ob = (size_t)rb * N + col;
        float2 r0 = *(const float2*)&resid[oa];
        float2 r1 = *(const float2*)&resid[ob];
        *(float2*)&C[oa] = make_float2(geluf(acc[i][j][0] + b0) + r0.x,
                                       geluf(acc[i][j][1] + b1) + r0.y);
        *(float2*)&C[ob] = make_float2(geluf(acc[i][j][2] + b0) + r1.x,
                                       geluf(acc[i][j][3] + b1) + r1.y);
      }
    }
  }
}
#define NT_SMEM3_128 (3*(256*32)*4)

// ================= GEMM TN (A scalar-LDS k-major, B ldmatrix), 3-stage ===========
template<int MT, int WMW>
__global__ __launch_bounds__(256, 2) void gemm_tn(const float* __restrict__ At,
    const float* __restrict__ B, float* __restrict__ C, int M, int N, int K,
    int lda, int sA, int sC, int nsplit) {
  constexpr int WNW = 8 / WMW;
  constexpr int WNT = 128 / WNW;
  constexpr int JF  = WNT / 8;
  constexpr int JF2 = JF / 2;
  constexpr int AST = MT + 8;
  constexpr int STG = 32 * AST + 128 * 32;
  const int z = blockIdx.z;
  const int b = z / nsplit, s = z - b * nsplit;
  const int Kp = K / nsplit;
  At += (size_t)b * sA + (size_t)(s * Kp) * lda;
  C  += (size_t)z * sC;
  extern __shared__ float sm[];
  const uint32_t sbase = smem_u32(sm);
  const int tid = threadIdx.x;
  const int wid = tid >> 5, lane = tid & 31;
  const int wm = wid % WMW, wn = wid / WMW;
  const int group = lane >> 2, tg = lane & 3;
  const int m0 = blockIdx.y * MT, n0 = blockIdx.x * 128;
  const int lr = tid >> 3, lk = tid & 7;
  const int akk = tid >> 3, amc = tid & 7;
  const int KC = Kp / 32;

  int b_row[JF2];
#pragma unroll
  for (int j2 = 0; j2 < JF2; j2++)
    b_row[j2] = wn * WNT + j2 * 16 + (lane & 7) + ((lane & 16) ? 8 : 0);
  const int b_qc = (lane & 8) ? 1 : 0;

  float acc[2][JF][4] = {};

#define TN_LOAD(c) do { \
    int k0 = (c) * 32; \
    float* stA_ = sm + ((c) % 3) * STG; \
    float* stB_ = stA_ + 32 * AST; \
    _Pragma("unroll") \
    for (int pass = 0; pass < MT/32; ++pass) { \
      int mc = amc + pass * 8; \
      cp16(stA_ + akk * AST + mc * 4, &At[(size_t)(k0 + akk) * lda + m0 + mc * 4]); \
    } \
    _Pragma("unroll") \
    for (int pass = 0; pass < 4; ++pass) { \
      int r = lr + pass * 32; \
      int sc = (lk ^ (r & 7)) * 4; \
      cp16z(stB_ + r * 32 + sc, &B[(size_t)(n0 + r) * K + s * Kp + k0 + lk * 4], n0 + r < N); \
    } \
    CP_COMMIT(); \
  } while (0)

  TN_LOAD(0);
  if (KC > 1) TN_LOAD(1);
  for (int c = 0; c < KC; ++c) {
    if (c + 1 < KC) CP_WAIT1(); else CP_WAIT0();
    __syncthreads();
    if (c + 2 < KC) TN_LOAD(c + 2);
    float (*Asr)[AST] = (float(*)[AST])(sm + (c % 3) * STG);
    const uint32_t stB = sbase + ((c % 3) * STG + 32 * AST) * 4;
#pragma unroll
    for (int ks = 0; ks < 4; ++ks) {
      int kk = ks * 8;
      uint32_t af[2][4], bfr[JF][2];
#pragma unroll
      for (int i = 0; i < 2; i++) {
        int mr = wm * 32 + i * 16;
        af[i][0] = __float_as_uint(Asr[kk + tg    ][mr + group    ]);
        af[i][1] = __float_as_uint(Asr[kk + tg    ][mr + group + 8]);
        af[i][2] = __float_as_uint(Asr[kk + tg + 4][mr + group    ]);
        af[i][3] = __float_as_uint(Asr[kk + tg + 4][mr + group + 8]);
      }
#pragma unroll
      for (int j2 = 0; j2 < JF2; j2++) {
        uint32_t bd = stB + b_row[j2] * 128 + ((((2 * ks + b_qc) ^ (b_row[j2] & 7))) << 4);
        uint32_t r0, r1, r2, r3;
        LDSM4(r0, r1, r2, r3, bd);
        bfr[2*j2][0] = r0; bfr[2*j2][1] = r1;
        bfr[2*j2+1][0] = r2; bfr[2*j2+1][1] = r3;
      }
#pragma unroll
      for (int i = 0; i < 2; i++)
#pragma unroll
        for (int j = 0; j < JF; j++)
          mma_tf32(acc[i][j], af[i], bfr[j]);
    }
  }
#undef TN_LOAD
#pragma unroll
  for (int i = 0; i < 2; i++) {
    int row0 = m0 + wm * 32 + i * 16 + group;
#pragma unroll
    for (int j = 0; j < JF; j++) {
      int col = n0 + wn * WNT + j * 8 + tg * 2;
      if (col < N) {
        *(float2*)&C[(size_t)row0 * N + col]       = make_float2(acc[i][j][0], acc[i][j][1]);
        *(float2*)&C[(size_t)(row0 + 8) * N + col] = make_float2(acc[i][j][2], acc[i][j][3]);
      }
    }
  }
}
#define TN_SMEM3_128 (3*(32*136 + 128*32)*4)
#define TN_SMEM3_64  (3*(32*72  + 128*32)*4)

// ================= split-K reduce for dbc =================
__global__ void reduce_dbc() {
  int i = blockIdx.x * 256 + threadIdx.x;
  const int per = BATCH*SEQ*DBC_W/4;
  if (i >= per) return;
  const float4* p = (const float4*)g_dbcp;
  int b = i / (SEQ*DBC_W/4);
  int off = i - b * (SEQ*DBC_W/4);
  float4 r = make_float4(0.f,0.f,0.f,0.f);
#pragma unroll
  for (int s = 0; s < XSPLIT; s++) {
    float4 v = p[(size_t)(b*XSPLIT + s) * (SEQ*DBC_W/4) + off];
    r.x += v.x; r.y += v.y; r.z += v.z; r.w += v.w;
  }
  ((float4*)g_dbc)[i] = r;
}

// ================= conv + silu + z-silu, transposed to [b,d,t] =================
__global__ void convz_kernel(const float* __restrict__ conv_w, const float* __restrict__ conv_b) {
  __shared__ float sx[67][33];
  __shared__ float sz[64][33];
  int b = blockIdx.z, t0 = blockIdx.x * 64, d0 = blockIdx.y * 32;
  int tid = threadIdx.y * 64 + threadIdx.x;
  for (int i = tid; i < 67*32; i += 256) {
    int r = i >> 5, c = i & 31;
    int t = t0 - 3 + r;
    sx[r][c] = (t >= 0) ? g_xz[(size_t)(b*SEQ + t)*2*DINNER + d0 + c] : 0.f;
  }
  for (int i = tid; i < 64*32; i += 256) {
    int r = i >> 5, c = i & 31;
    sz[r][c] = g_xz[(size_t)(b*SEQ + t0 + r)*2*DINNER + DINNER + d0 + c];
  }
  __syncthreads();
  int tx = threadIdx.x;
#pragma unroll
  for (int i = 0; i < 8; i++) {
    int dl = threadIdx.y * 8 + i;
    int d = d0 + dl;
    float w0 = conv_w[d*4+0], w1 = conv_w[d*4+1], w2 = conv_w[d*4+2], w3 = conv_w[d*4+3];
    float acc = conv_b[d];
    acc += sx[tx+0][dl]*w0 + sx[tx+1][dl]*w1 + sx[tx+2][dl]*w2 + sx[tx+3][dl]*w3;
    size_t o = (size_t)(b*DINNER + d)*SEQ + t0 + tx;
    g_ut[o] = siluf(acc);
    g_zt[o] = siluf(sz[tx][dl]);
  }
}

// ================= selective scan with inline delta (fused delta_mma) ============
// delta = softplus(dot(dbc[t][0:32], dtW[d]) + dtB[d]) computed per lane from the
// same sBC staging used for B/C. Serial chain is FFMA-only on precomputed dA/w.
__global__ void scan_kernel(const float* __restrict__ Dw, const float* __restrict__ A_log,
                            const float* __restrict__ dtW, const float* __restrict__ dtB) {
  int warp = threadIdx.x >> 5, lane = threadIdx.x & 31;
  int g = blockIdx.x * 8 + warp;
  int b = g >> 10, d = g & 1023;
  __shared__ float sBC[32][97];        // full 96 dbc cols, stride 97 (conflict-free)
  __shared__ float sP[8][32][34];
  __shared__ float sw[8][33];          // dtW row per warp
  float An = -__expf(A_log[d*DSTATE + lane]);
  float Dd = Dw[d];
  float bias_d = dtB[d];
  sw[warp][lane] = dtW[d*DTRANK + lane];
  float h = 0.f;
  const float* ut  = g_ut + (size_t)(b*DINNER + d)*SEQ;
  const float* ztp = g_zt + (size_t)(b*DINNER + d)*SEQ;
  float*       ytp = g_yt + (size_t)(b*DINNER + d)*SEQ;
  const int sr = threadIdx.x >> 3;           // staging row 0..31
  const int sc0 = (threadIdx.x & 7) * 12;    // staging col base
  __syncwarp();

  for (int t0 = 0; t0 < SEQ; t0 += 32) {
    __syncthreads();
    {
      const float* src = &g_dbc[((size_t)(b*SEQ + t0 + sr))*DBC_W + sc0];
#pragma unroll
      for (int j = 0; j < 12; j++) sBC[sr][sc0 + j] = src[j];
    }
    __syncthreads();
    float du = ut[t0 + lane];
    float sz = ztp[t0 + lane];
    // inline delta: dot over dt-rank 32 (parallel, off-chain)
    float acc = bias_d;
#pragma unroll
    for (int r = 0; r < 32; r++)
      acc = fmaf(sBC[lane][r], sw[warp][r], acc);
    float dd = softplusf(acc);
    float dtu = dd * du;
    // precompute dA and w for all 32 steps (off the serial chain)
    float dAv[32], wv[32];
#pragma unroll
    for (int s = 0; s < 32; s++) {
      float delta_t = __shfl_sync(0xffffffffu, dd, s);
      float dtu_t   = __shfl_sync(0xffffffffu, dtu, s);
      dAv[s] = __expf(delta_t * An);
      wv[s]  = dtu_t * sBC[s][32 + lane];
    }
    // serial chain: pure FFMA
#pragma unroll
    for (int s = 0; s < 32; s++) {
      h = fmaf(dAv[s], h, wv[s]);
      sP[warp][s][lane] = h * sBC[s][64 + lane];
    }
    __syncwarp();
    float y = du * Dd;
#pragma unroll
    for (int i = 0; i < 32; i++) {
      int c = (lane + i) & 31;
      y += sP[warp][lane][c];
    }
    ytp[t0 + lane] = y * sz;
  }
}

// ================= layernorm =================
__global__ void ln_kernel(const float* __restrict__ lnw, const float* __restrict__ lnb) {
  int row = blockIdx.x;
  const float* y = g_y2 + (size_t)row * DMODEL;
  float*       o = g_yn + (size_t)row * DMODEL;
  int tid = threadIdx.x;
  int lane = tid & 31, wid = tid >> 5;
  float v[4], s = 0.f, s2 = 0.f;
#pragma unroll
  for (int i = 0; i < 4; i++) {
    float x = y[tid + i*128];
    v[i] = x; s += x; s2 += x*x;
  }
#pragma unroll
  for (int off = 16; off >= 1; off >>= 1) {
    s  += __shfl_xor_sync(0xffffffffu, s, off);
    s2 += __shfl_xor_sync(0xffffffffu, s2, off);
  }
  __shared__ float sh[10];
  if (lane == 0) { sh[wid] = s; sh[4 + wid] = s2; }
  __syncthreads();
  if (tid == 0) {
    float ts = sh[0] + sh[1] + sh[2] + sh[3];
    float ts2 = sh[4] + sh[5] + sh[6] + sh[7];
    float mu = ts * (1.f/DMODEL);
    float var = ts2 * (1.f/DMODEL) - mu*mu;
    sh[8] = mu;
    sh[9] = rsqrtf(var + 1e-5f);
  }
  __syncthreads();
  float mu = sh[8], inv = sh[9];
#pragma unroll
  for (int i = 0; i < 4; i++) {
    int c = tid + i*128;
    o[c] = (v[i] - mu) * inv * lnw[c] + lnb[c];
  }
}

// ================= launch =================
extern "C" void kernel_launch(void* const* d_in, const int* in_sizes, int n_in,
                              void* d_out, int out_size) {
  const float* tokens     = (const float*)d_in[0];
  const float* in_proj_w  = (const float*)d_in[1];
  const float* conv_w     = (const float*)d_in[2];
  const float* conv_b     = (const float*)d_in[3];
  const float* x_proj_w   = (const float*)d_in[4];
  const float* dt_proj_w  = (const float*)d_in[5];
  const float* dt_proj_b  = (const float*)d_in[6];
  const float* A_log      = (const float*)d_in[7];
  const float* Dw         = (const float*)d_in[8];
  const float* out_proj_w = (const float*)d_in[9];
  const float* ln_w       = (const float*)d_in[10];
  const float* ln_b       = (const float*)d_in[11];
  const float* lin_w      = (const float*)d_in[12];
  const float* lin_b      = (const float*)d_in[13];
  float* out = (float*)d_out;

  float *p_xz, *p_ut, *p_dbcp, *p_dbc, *p_yt, *p_y2, *p_yn;
  cudaGetSymbolAddress((void**)&p_xz,   g_xz);
  cudaGetSymbolAddress((void**)&p_ut,   g_ut);
  cudaGetSymbolAddress((void**)&p_dbcp, g_dbcp);
  cudaGetSymbolAddress((void**)&p_dbc,  g_dbc);
  cudaGetSymbolAddress((void**)&p_yt,   g_yt);
  cudaGetSymbolAddress((void**)&p_y2,   g_y2);
  cudaGetSymbolAddress((void**)&p_yn,   g_yn);

  cudaFuncSetAttribute(gemm_nt<128,4>, cudaFuncAttributeMaxDynamicSharedMemorySize, NT_SMEM3_128);
  cudaFuncSetAttribute(gemm_tn<128,4>, cudaFuncAttributeMaxDynamicSharedMemorySize, TN_SMEM3_128);
  cudaFuncSetAttribute(gemm_tn<64,2>,  cudaFuncAttributeMaxDynamicSharedMemorySize, TN_SMEM3_64);

  // 1. xz = perm(tokens) @ in_proj_w^T
  gemm_nt<128,4><<<dim3(2*DINNER/128, NROWS/128), 256, NT_SMEM3_128>>>(
      tokens, in_proj_w, p_xz, NROWS, 2*DINNER, DMODEL, 1, 0, nullptr, nullptr);
  // 2. conv+silu -> ut ; silu(z) -> zt
  convz_kernel<<<dim3(SEQ/64, DINNER/32, BATCH), dim3(64,4)>>>(conv_w, conv_b);
  // 3. dbc partials (split-K=4)
  gemm_tn<128,4><<<dim3(1, SEQ/128, BATCH*XSPLIT), 256, TN_SMEM3_128>>>(
      p_ut, x_proj_w, p_dbcp, SEQ, DBC_W, DINNER, SEQ, DINNER*SEQ, SEQ*DBC_W, XSPLIT);
  // 3b. reduce partials
  reduce_dbc<<<(BATCH*SEQ*DBC_W/4 + 255)/256, 256>>>();
  // 4. scan (delta computed inline; delta_mma kernel and deltat tensor eliminated)
  scan_kernel<<<NROWS/8, 256>>>(Dw, A_log, dt_proj_w, dt_proj_b);
  // 5. y2 = y @ out_proj_w^T
  gemm_tn<64,2><<<dim3(DMODEL/128, SEQ/64, BATCH), 256, TN_SMEM3_64>>>(
      p_yt, out_proj_w, p_y2, SEQ, DMODEL, DINNER, SEQ, DINNER*SEQ, SEQ*DMODEL, 1);
  // 6. layernorm
  ln_kernel<<<NROWS, 128>>>(ln_w, ln_b);
  // 7. out = gelu(yn @ lin_w^T + lin_b) + residual
  gemm_nt<128,4><<<dim3(DMODEL/128, NROWS/128), 256, NT_SMEM3_128>>>(
      p_yn, lin_w, out, NROWS, DMODEL, DMODEL, 0, 1, lin_b, tokens);
}

// round 13
// speedup vs baseline: 1.0718x; 1.0718x over previous
#include <cuda_runtime.h>
#include <cstdint>
#include <math.h>

#define BATCH  4
#define SEQ    1024
#define DMODEL 512
#define DINNER 1024
#define DSTATE 32
#define DTRANK 32
#define DBC_W  96
#define NROWS  (BATCH*SEQ)   // 4096
#define XSPLIT 4

// ================= scratch =================
__device__ float g_xz    [BATCH*SEQ*DINNER];     // x half only (z fused into epilogue)
__device__ float g_ut    [BATCH*DINNER*SEQ];
__device__ float g_zt    [BATCH*DINNER*SEQ];
__device__ float g_dbcp  [XSPLIT*BATCH*SEQ*DBC_W];
__device__ float g_dbc   [BATCH*SEQ*DBC_W];
__device__ float g_deltat[BATCH*DINNER*SEQ];
__device__ float g_yt    [BATCH*DINNER*SEQ];
__device__ float g_y2    [BATCH*SEQ*DMODEL];
__device__ float g_yn    [BATCH*SEQ*DMODEL];

__device__ __forceinline__ int perm_src(int p) {
  int r = p >> 5, c = p & 31;
  if (r & 1) c = 31 - c;
  return (r << 5) | c;
}
__device__ __forceinline__ int remap_row(int m) {
  return (m & ~(SEQ - 1)) + perm_src(m & (SEQ - 1));
}
__device__ __forceinline__ float softplusf(float x) {
  return fmaxf(x, 0.f) + __logf(1.f + __expf(-fabsf(x)));
}
__device__ __forceinline__ float siluf(float x) {
  return __fdividef(x, 1.f + __expf(-x));
}
__device__ __forceinline__ float fast_erff(float x) {
  float ax = fabsf(x);
  float t = __frcp_rn(fmaf(0.3275911f, ax, 1.f));
  float p = t * fmaf(t, fmaf(t, fmaf(t, fmaf(t, 1.061405429f, -1.453152027f),
                     1.421413741f), -0.284496736f), 0.254829592f);
  float r = 1.f - p * __expf(-ax * ax);
  return copysignf(r, x);
}
__device__ __forceinline__ float geluf(float x) {
  return 0.5f * x * (1.f + fast_erff(x * 0.70710678118654752f));
}
__device__ __forceinline__ uint32_t smem_u32(const void* p) {
  uint32_t a;
  asm("{ .reg .u64 t; cvta.to.shared.u64 t, %1; cvt.u32.u64 %0, t; }" : "=r"(a) : "l"(p));
  return a;
}
__device__ __forceinline__ void cp16(void* dst, const void* src) {
  asm volatile("cp.async.cg.shared.global [%0], [%1], 16;"
               :: "r"(smem_u32(dst)), "l"(src));
}
__device__ __forceinline__ void cp16z(void* dst, const void* src, bool valid) {
  int sz = valid ? 16 : 0;
  asm volatile("cp.async.cg.shared.global [%0], [%1], 16, %2;"
               :: "r"(smem_u32(dst)), "l"(src), "r"(sz));
}
#define CP_COMMIT() asm volatile("cp.async.commit_group;" ::: "memory")
#define CP_WAIT1()  asm volatile("cp.async.wait_group 1;" ::: "memory")
#define CP_WAIT0()  asm volatile("cp.async.wait_group 0;" ::: "memory")

#define LDSM4(r0, r1, r2, r3, addr) \
  asm volatile("ldmatrix.sync.aligned.m8n8.x4.shared.b16 {%0,%1,%2,%3}, [%4];" \
    : "=r"(r0), "=r"(r1), "=r"(r2), "=r"(r3) : "r"(addr))

__device__ __forceinline__ void mma_tf32(float* c, const uint32_t* a, const uint32_t* b) {
  asm volatile(
    "mma.sync.aligned.m16n8k8.row.col.f32.tf32.tf32.f32 "
    "{%0,%1,%2,%3}, {%4,%5,%6,%7}, {%8,%9}, {%0,%1,%2,%3};"
    : "+f"(c[0]), "+f"(c[1]), "+f"(c[2]), "+f"(c[3])
    : "r"(a[0]), "r"(a[1]), "r"(a[2]), "r"(a[3]), "r"(b[0]), "r"(b[1]));
}

// ================= GEMM NT (MT=128, swizzled smem + ldmatrix, 3-stage) ==========
// C[M,N] = A[M,K] @ B[N,K]^T.
// epi=0: plain rows to C (ld=N).
// epi=1: gelu+bias+residual with inverse-perm scatter (final stage).
// epi=2: in_proj fused: cols < N/2 -> C rows (ld=N/2); cols >= N/2 -> silu +
//        smem transpose -> g_zt[b,d,t] (z half of convz fused here).
#define NT_STAGE (256*32)
#define NT_SMEM3 (3*NT_STAGE*4)
__global__ __launch_bounds__(256, 2) void gemm_nt(const float* __restrict__ A,
    const float* __restrict__ B, float* __restrict__ C, int M, int N, int K,
    int gatherA, int epi, const float* __restrict__ bias,
    const float* __restrict__ resid) {
  extern __shared__ float sm[];
  const uint32_t sbase = smem_u32(sm);
  const int tid = threadIdx.x;
  const int wid = tid >> 5, lane = tid & 31;
  const int wm = wid & 3, wn = wid >> 2;
  const int group = lane >> 2, tg = lane & 3;
  const int m0 = blockIdx.y * 128, n0 = blockIdx.x * 128;
  const int lr = tid >> 3, lk = tid & 7;
  const int KC = K / 32;

  int a_row[2], b_row[4];
#pragma unroll
  for (int i = 0; i < 2; i++)
    a_row[i] = wm * 32 + i * 16 + (lane & 7) + ((lane & 8) ? 8 : 0);
#pragma unroll
  for (int j2 = 0; j2 < 4; j2++)
    b_row[j2] = wn * 64 + j2 * 16 + (lane & 7) + ((lane & 16) ? 8 : 0);
  const int a_qc = (lane & 16) ? 1 : 0;
  const int b_qc = (lane & 8) ? 1 : 0;

  float acc[2][8][4] = {};

  int arow[4];
#pragma unroll
  for (int pass = 0; pass < 4; ++pass) {
    int m = m0 + lr + pass * 32;
    arow[pass] = gatherA ? remap_row(m) : m;
  }

#define NT_LOAD(c) do { \
    int k0 = (c) * 32; \
    float* st = sm + ((c) % 3) * NT_STAGE; \
    _Pragma("unroll") \
    for (int pass = 0; pass < 4; ++pass) { \
      int r = lr + pass * 32; \
      int sc = (lk ^ (r & 7)) * 4; \
      cp16(st + r * 32 + sc, &A[(size_t)arow[pass] * K + k0 + lk * 4]); \
      cp16(st + 128 * 32 + r * 32 + sc, &B[(size_t)(n0 + r) * K + k0 + lk * 4]); \
    } \
    CP_COMMIT(); \
  } while (0)

  NT_LOAD(0);
  if (KC > 1) NT_LOAD(1);
  for (int c = 0; c < KC; ++c) {
    if (c + 1 < KC) CP_WAIT1(); else CP_WAIT0();
    __syncthreads();
    if (c + 2 < KC) NT_LOAD(c + 2);
    const uint32_t stA = sbase + ((c % 3) * NT_STAGE) * 4;
    const uint32_t stB = stA + 128 * 32 * 4;
#pragma unroll
    for (int ks = 0; ks < 4; ++ks) {
      uint32_t af[2][4], bfr[8][2];
#pragma unroll
      for (int i = 0; i < 2; i++) {
        uint32_t ad = stA + a_row[i] * 128 + ((((2 * ks + a_qc) ^ (a_row[i] & 7))) << 4);
        LDSM4(af[i][0], af[i][1], af[i][2], af[i][3], ad);
      }
#pragma unroll
      for (int j2 = 0; j2 < 4; j2++) {
        uint32_t bd = stB + b_row[j2] * 128 + ((((2 * ks + b_qc) ^ (b_row[j2] & 7))) << 4);
        uint32_t r0, r1, r2, r3;
        LDSM4(r0, r1, r2, r3, bd);
        bfr[2*j2][0] = r0; bfr[2*j2][1] = r1;
        bfr[2*j2+1][0] = r2; bfr[2*j2+1][1] = r3;
      }
#pragma unroll
      for (int i = 0; i < 2; i++)
#pragma unroll
        for (int j = 0; j < 8; j++)
          mma_tf32(acc[i][j], af[i], bfr[j]);
    }
  }
#undef NT_LOAD

  if (epi == 1) {
#pragma unroll
    for (int i = 0; i < 2; i++) {
      int row0 = m0 + wm * 32 + i * 16 + group;
      int ra = remap_row(row0), rb = remap_row(row0 + 8);
#pragma unroll
      for (int j = 0; j < 8; j++) {
        int col = n0 + wn * 64 + j * 8 + tg * 2;
        float b0 = bias[col], b1 = bias[col + 1];
        size_t oa = (size_t)ra * N + col, ob = (size_t)rb * N + col;
        float2 r0 = *(const float2*)&resid[oa];
        float2 r1 = *(const float2*)&resid[ob];
        *(float2*)&C[oa] = make_float2(geluf(acc[i][j][0] + b0) + r0.x,
                                       geluf(acc[i][j][1] + b1) + r0.y);
        *(float2*)&C[ob] = make_float2(geluf(acc[i][j][2] + b0) + r1.x,
                                       geluf(acc[i][j][3] + b1) + r1.y);
      }
    }
  } else if (epi == 2 && n0 >= N / 2) {
    // z half: silu + transpose to g_zt[b,d,t] via smem
    float (*ts)[132] = (float(*)[132])sm;
    __syncthreads();   // mainloop smem fully consumed
#pragma unroll
    for (int i = 0; i < 2; i++) {
      int rowL = wm * 32 + i * 16 + group;
#pragma unroll
      for (int j = 0; j < 8; j++) {
        int colL = wn * 64 + j * 8 + tg * 2;
        ts[rowL][colL]     = acc[i][j][0];
        ts[rowL][colL + 1] = acc[i][j][1];
        ts[rowL + 8][colL]     = acc[i][j][2];
        ts[rowL + 8][colL + 1] = acc[i][j][3];
      }
    }
    __syncthreads();
    int b = m0 >> 10;          // m0 / SEQ
    int t0 = m0 & (SEQ - 1);
    int d0 = n0 - N / 2;
    for (int q = tid; q < 128 * 32; q += 256) {
      int dc = q >> 5;
      int tq = (q & 31) * 4;
      float4 v;
      v.x = siluf(ts[tq + 0][dc]);
      v.y = siluf(ts[tq + 1][dc]);
      v.z = siluf(ts[tq + 2][dc]);
      v.w = siluf(ts[tq + 3][dc]);
      *(float4*)&g_zt[(size_t)(b * DINNER + d0 + dc) * SEQ + t0 + tq] = v;
    }
  } else {
    // epi==0, or epi==2 x half: plain row store (ld = N for epi0, N/2 for epi2)
    int ld = (epi == 2) ? N / 2 : N;
#pragma unroll
    for (int i = 0; i < 2; i++) {
      int row0 = m0 + wm * 32 + i * 16 + group;
#pragma unroll
      for (int j = 0; j < 8; j++) {
        int col = n0 + wn * 64 + j * 8 + tg * 2;
        *(float2*)&C[(size_t)row0 * ld + col]       = make_float2(acc[i][j][0], acc[i][j][1]);
        *(float2*)&C[(size_t)(row0 + 8) * ld + col] = make_float2(acc[i][j][2], acc[i][j][3]);
      }
    }
  }
}

// ================= GEMM TN (A scalar-LDS k-major, B ldmatrix), 3-stage ===========
template<int MT, int WMW>
__global__ __launch_bounds__(256, 2) void gemm_tn(const float* __restrict__ At,
    const float* __restrict__ B, float* __restrict__ C, int M, int N, int K,
    int lda, int sA, int sC, int nsplit) {
  constexpr int WNW = 8 / WMW;
  constexpr int WNT = 128 / WNW;
  constexpr int JF  = WNT / 8;
  constexpr int JF2 = JF / 2;
  constexpr int AST = MT + 8;
  constexpr int STG = 32 * AST + 128 * 32;
  const int z = blockIdx.z;
  const int b = z / nsplit, s = z - b * nsplit;
  const int Kp = K / nsplit;
  At += (size_t)b * sA + (size_t)(s * Kp) * lda;
  C  += (size_t)z * sC;
  extern __shared__ float sm[];
  const uint32_t sbase = smem_u32(sm);
  const int tid = threadIdx.x;
  const int wid = tid >> 5, lane = tid & 31;
  const int wm = wid % WMW, wn = wid / WMW;
  const int group = lane >> 2, tg = lane & 3;
  const int m0 = blockIdx.y * MT, n0 = blockIdx.x * 128;
  const int lr = tid >> 3, lk = tid & 7;
  const int akk = tid >> 3, amc = tid & 7;
  const int KC = Kp / 32;

  int b_row[JF2];
#pragma unroll
  for (int j2 = 0; j2 < JF2; j2++)
    b_row[j2] = wn * WNT + j2 * 16 + (lane & 7) + ((lane & 16) ? 8 : 0);
  const int b_qc = (lane & 8) ? 1 : 0;

  float acc[2][JF][4] = {};

#define TN_LOAD(c) do { \
    int k0 = (c) * 32; \
    float* stA_ = sm + ((c) % 3) * STG; \
    float* stB_ = stA_ + 32 * AST; \
    _Pragma("unroll") \
    for (int pass = 0; pass < MT/32; ++pass) { \
      int mc = amc + pass * 8; \
      cp16(stA_ + akk * AST + mc * 4, &At[(size_t)(k0 + akk) * lda + m0 + mc * 4]); \
    } \
    _Pragma("unroll") \
    for (int pass = 0; pass < 4; ++pass) { \
      int r = lr + pass * 32; \
      int sc = (lk ^ (r & 7)) * 4; \
      cp16z(stB_ + r * 32 + sc, &B[(size_t)(n0 + r) * K + s * Kp + k0 + lk * 4], n0 + r < N); \
    } \
    CP_COMMIT(); \
  } while (0)

  TN_LOAD(0);
  if (KC > 1) TN_LOAD(1);
  for (int c = 0; c < KC; ++c) {
    if (c + 1 < KC) CP_WAIT1(); else CP_WAIT0();
    __syncthreads();
    if (c + 2 < KC) TN_LOAD(c + 2);
    float (*Asr)[AST] = (float(*)[AST])(sm + (c % 3) * STG);
    const uint32_t stB = sbase + ((c % 3) * STG + 32 * AST) * 4;
#pragma unroll
    for (int ks = 0; ks < 4; ++ks) {
      int kk = ks * 8;
      uint32_t af[2][4], bfr[JF][2];
#pragma unroll
      for (int i = 0; i < 2; i++) {
        int mr = wm * 32 + i * 16;
        af[i][0] = __float_as_uint(Asr[kk + tg    ][mr + group    ]);
        af[i][1] = __float_as_uint(Asr[kk + tg    ][mr + group + 8]);
        af[i][2] = __float_as_uint(Asr[kk + tg + 4][mr + group    ]);
        af[i][3] = __float_as_uint(Asr[kk + tg + 4][mr + group + 8]);
      }
#pragma unroll
      for (int j2 = 0; j2 < JF2; j2++) {
        uint32_t bd = stB + b_row[j2] * 128 + ((((2 * ks + b_qc) ^ (b_row[j2] & 7))) << 4);
        uint32_t r0, r1, r2, r3;
        LDSM4(r0, r1, r2, r3, bd);
        bfr[2*j2][0] = r0; bfr[2*j2][1] = r1;
        bfr[2*j2+1][0] = r2; bfr[2*j2+1][1] = r3;
      }
#pragma unroll
      for (int i = 0; i < 2; i++)
#pragma unroll
        for (int j = 0; j < JF; j++)
          mma_tf32(acc[i][j], af[i], bfr[j]);
    }
  }
#undef TN_LOAD
#pragma unroll
  for (int i = 0; i < 2; i++) {
    int row0 = m0 + wm * 32 + i * 16 + group;
#pragma unroll
    for (int j = 0; j < JF; j++) {
      int col = n0 + wn * WNT + j * 8 + tg * 2;
      if (col < N) {
        *(float2*)&C[(size_t)row0 * N + col]       = make_float2(acc[i][j][0], acc[i][j][1]);
        *(float2*)&C[(size_t)(row0 + 8) * N + col] = make_float2(acc[i][j][2], acc[i][j][3]);
      }
    }
  }
}
#define TN_SMEM3_128 (3*(32*136 + 128*32)*4)
#define TN_SMEM3_64  (3*(32*72  + 128*32)*4)

// ================= split-K reduce for dbc =================
__global__ void reduce_dbc() {
  int i = blockIdx.x * 256 + threadIdx.x;
  const int per = BATCH*SEQ*DBC_W/4;
  if (i >= per) return;
  const float4* p = (const float4*)g_dbcp;
  int b = i / (SEQ*DBC_W/4);
  int off = i - b * (SEQ*DBC_W/4);
  float4 r = make_float4(0.f,0.f,0.f,0.f);
#pragma unroll
  for (int s = 0; s < XSPLIT; s++) {
    float4 v = p[(size_t)(b*XSPLIT + s) * (SEQ*DBC_W/4) + off];
    r.x += v.x; r.y += v.y; r.z += v.z; r.w += v.w;
  }
  ((float4*)g_dbc)[i] = r;
}

// ================= delta via mma (128d x 64t tiles) =================
__global__ __launch_bounds__(256) void delta_mma(const float* __restrict__ W,
    const float* __restrict__ dbc, const float* __restrict__ bias,
    float* __restrict__ outp) {
  __shared__ float As[128][36];
  __shared__ float Bs[64][36];
  const int b = blockIdx.z;
  const int tid = threadIdx.x;
  const int wid = tid >> 5, lane = tid & 31;
  const int wm = wid & 3, wn = wid >> 2;
  const int group = lane >> 2, tg = lane & 3;
  const int m0 = blockIdx.y * 128, n0 = blockIdx.x * 64;

  const float* Bb = dbc + (size_t)b * SEQ * DBC_W;
#pragma unroll
  for (int pass = 0; pass < 4; ++pass) {
    int i = tid + pass * 256;
    int r = i >> 3, q = i & 7;
    *(float4*)&As[r][q * 4] = *(const float4*)&W[(size_t)(m0 + r) * DTRANK + q * 4];
  }
#pragma unroll
  for (int pass = 0; pass < 2; ++pass) {
    int i = tid + pass * 256;
    int r = i >> 3, q = i & 7;
    *(float4*)&Bs[r][q * 4] = *(const float4*)&Bb[(size_t)(n0 + r) * DBC_W + q * 4];
  }
  __syncthreads();

  float acc[2][4][4] = {};
#pragma unroll
  for (int ks = 0; ks < 4; ++ks) {
    int kk = ks * 8;
    uint32_t af[2][4], bfr[4][2];
#pragma unroll
    for (int i = 0; i < 2; i++) {
      int mr = wm * 32 + i * 16;
      af[i][0] = __float_as_uint(As[mr + group    ][kk + tg    ]);
      af[i][1] = __float_as_uint(As[mr + group + 8][kk + tg    ]);
      af[i][2] = __float_as_uint(As[mr + group    ][kk + tg + 4]);
      af[i][3] = __float_as_uint(As[mr + group + 8][kk + tg + 4]);
    }
#pragma unroll
    for (int j = 0; j < 4; j++) {
      int nr = wn * 32 + j * 8;
      bfr[j][0] = __float_as_uint(Bs[nr + group][kk + tg    ]);
      bfr[j][1] = __float_as_uint(Bs[nr + group][kk + tg + 4]);
    }
#pragma unroll
    for (int i = 0; i < 2; i++)
#pragma unroll
      for (int j = 0; j < 4; j++)
        mma_tf32(acc[i][j], af[i], bfr[j]);
  }
  float* ob = outp + (size_t)b * DINNER * SEQ;
#pragma unroll
  for (int i = 0; i < 2; i++) {
    int d0 = m0 + wm * 32 + i * 16 + group;
    float ba = bias[d0], bb2 = bias[d0 + 8];
#pragma unroll
    for (int j = 0; j < 4; j++) {
      int t = n0 + wn * 32 + j * 8 + tg * 2;
      *(float2*)&ob[(size_t)d0 * SEQ + t] =
        make_float2(softplusf(acc[i][j][0] + ba), softplusf(acc[i][j][1] + ba));
      *(float2*)&ob[(size_t)(d0 + 8) * SEQ + t] =
        make_float2(softplusf(acc[i][j][2] + bb2), softplusf(acc[i][j][3] + bb2));
    }
  }
}

// ================= conv + silu (x half only; z handled in in_proj epilogue) ======
__global__ void convz_kernel(const float* __restrict__ conv_w, const float* __restrict__ conv_b) {
  __shared__ float sx[67][33];
  int b = blockIdx.z, t0 = blockIdx.x * 64, d0 = blockIdx.y * 32;
  int tid = threadIdx.y * 64 + threadIdx.x;
  for (int i = tid; i < 67*32; i += 256) {
    int r = i >> 5, c = i & 31;
    int t = t0 - 3 + r;
    sx[r][c] = (t >= 0) ? g_xz[(size_t)(b*SEQ + t)*DINNER + d0 + c] : 0.f;
  }
  __syncthreads();
  int tx = threadIdx.x;
#pragma unroll
  for (int i = 0; i < 8; i++) {
    int dl = threadIdx.y * 8 + i;
    int d = d0 + dl;
    float w0 = conv_w[d*4+0], w1 = conv_w[d*4+1], w2 = conv_w[d*4+2], w3 = conv_w[d*4+3];
    float acc = conv_b[d];
    acc += sx[tx+0][dl]*w0 + sx[tx+1][dl]*w1 + sx[tx+2][dl]*w2 + sx[tx+3][dl]*w3;
    g_ut[(size_t)(b*DINNER + d)*SEQ + t0 + tx] = siluf(acc);
  }
}

// ================= selective scan (R8 shfl version — known best) =================
__global__ void scan_kernel(const float* __restrict__ Dw, const float* __restrict__ A_log) {
  int warp = threadIdx.x >> 5, lane = threadIdx.x & 31;
  int g = blockIdx.x * 8 + warp;
  int b = g >> 10, d = g & 1023;
  __shared__ float sBC[32][64];
  __shared__ float sP[8][32][34];
  float An = -__expf(A_log[d*DSTATE + lane]);
  float Dd = Dw[d];
  float h = 0.f;
  const float* ut  = g_ut     + (size_t)(b*DINNER + d)*SEQ;
  const float* dtp = g_deltat + (size_t)(b*DINNER + d)*SEQ;
  const float* ztp = g_zt     + (size_t)(b*DINNER + d)*SEQ;
  float*       ytp = g_yt     + (size_t)(b*DINNER + d)*SEQ;

  for (int t0 = 0; t0 < SEQ; t0 += 32) {
    __syncthreads();
    for (int i = threadIdx.x; i < 32*64; i += 256) {
      int s = i >> 6, c = i & 63;
      sBC[s][c] = g_dbc[(size_t)(b*SEQ + t0 + s)*DBC_W + DSTATE + c];
    }
    __syncthreads();
    float du = ut[t0 + lane];
    float dd = dtp[t0 + lane];
    float sz = ztp[t0 + lane];
#pragma unroll 8
    for (int s = 0; s < 32; s++) {
      float delta_t = __shfl_sync(0xffffffffu, dd, s);
      float u_t     = __shfl_sync(0xffffffffu, du, s);
      float dA = __expf(delta_t * An);
      h = fmaf(dA, h, delta_t * u_t * sBC[s][lane]);
      sP[warp][s][lane] = h * sBC[s][32 + lane];
    }
    __syncwarp();
    float y = du * Dd;
#pragma unroll
    for (int i = 0; i < 32; i++) {
      int c = (lane + i) & 31;
      y += sP[warp][lane][c];
    }
    ytp[t0 + lane] = y * sz;
  }
}

// ================= layernorm =================
__global__ void ln_kernel(const float* __restrict__ lnw, const float* __restrict__ lnb) {
  int row = blockIdx.x;
  const float* y = g_y2 + (size_t)row * DMODEL;
  float*       o = g_yn + (size_t)row * DMODEL;
  int tid = threadIdx.x;
  int lane = tid & 31, wid = tid >> 5;
  float v[4], s = 0.f, s2 = 0.f;
#pragma unroll
  for (int i = 0; i < 4; i++) {
    float x = y[tid + i*128];
    v[i] = x; s += x; s2 += x*x;
  }
#pragma unroll
  for (int off = 16; off >= 1; off >>= 1) {
    s  += __shfl_xor_sync(0xffffffffu, s, off);
    s2 += __shfl_xor_sync(0xffffffffu, s2, off);
  }
  __shared__ float sh[10];
  if (lane == 0) { sh[wid] = s; sh[4 + wid] = s2; }
  __syncthreads();
  if (tid == 0) {
    float ts = sh[0] + sh[1] + sh[2] + sh[3];
    float ts2 = sh[4] + sh[5] + sh[6] + sh[7];
    float mu = ts * (1.f/DMODEL);
    float var = ts2 * (1.f/DMODEL) - mu*mu;
    sh[8] = mu;
    sh[9] = rsqrtf(var + 1e-5f);
  }
  __syncthreads();
  float mu = sh[8], inv = sh[9];
#pragma unroll
  for (int i = 0; i < 4; i++) {
    int c = tid + i*128;
    o[c] = (v[i] - mu) * inv * lnw[c] + lnb[c];
  }
}

// ================= launch =================
extern "C" void kernel_launch(void* const* d_in, const int* in_sizes, int n_in,
                              void* d_out, int out_size) {
  const float* tokens     = (const float*)d_in[0];
  const float* in_proj_w  = (const float*)d_in[1];
  const float* conv_w     = (const float*)d_in[2];
  const float* conv_b     = (const float*)d_in[3];
  const float* x_proj_w   = (const float*)d_in[4];
  const float* dt_proj_w  = (const float*)d_in[5];
  const float* dt_proj_b  = (const float*)d_in[6];
  const float* A_log      = (const float*)d_in[7];
  const float* Dw         = (const float*)d_in[8];
  const float* out_proj_w = (const float*)d_in[9];
  const float* ln_w       = (const float*)d_in[10];
  const float* ln_b       = (const float*)d_in[11];
  const float* lin_w      = (const float*)d_in[12];
  const float* lin_b      = (const float*)d_in[13];
  float* out = (float*)d_out;

  float *p_xz, *p_ut, *p_dbcp, *p_dbc, *p_deltat, *p_yt, *p_y2, *p_yn;
  cudaGetSymbolAddress((void**)&p_xz,     g_xz);
  cudaGetSymbolAddress((void**)&p_ut,     g_ut);
  cudaGetSymbolAddress((void**)&p_dbcp,   g_dbcp);
  cudaGetSymbolAddress((void**)&p_dbc,    g_dbc);
  cudaGetSymbolAddress((void**)&p_deltat, g_deltat);
  cudaGetSymbolAddress((void**)&p_yt,     g_yt);
  cudaGetSymbolAddress((void**)&p_y2,     g_y2);
  cudaGetSymbolAddress((void**)&p_yn,     g_yn);

  cudaFuncSetAttribute(gemm_nt, cudaFuncAttributeMaxDynamicSharedMemorySize, NT_SMEM3);
  cudaFuncSetAttribute(gemm_tn<128,4>, cudaFuncAttributeMaxDynamicSharedMemorySize, TN_SMEM3_128);
  cudaFuncSetAttribute(gemm_tn<64,2>,  cudaFuncAttributeMaxDynamicSharedMemorySize, TN_SMEM3_64);

  // 1. xz = perm(tokens) @ in_proj_w^T ; x half -> g_xz rows, z half -> silu+T -> g_zt
  gemm_nt<<<dim3(2*DINNER/128, NROWS/128), 256, NT_SMEM3>>>(
      tokens, in_proj_w, p_xz, NROWS, 2*DINNER, DMODEL, 1, 2, nullptr, nullptr);
  // 2. conv+silu -> ut (x half only)
  convz_kernel<<<dim3(SEQ/64, DINNER/32, BATCH), dim3(64,4)>>>(conv_w, conv_b);
  // 3. dbc partials (split-K=4)
  gemm_tn<128,4><<<dim3(1, SEQ/128, BATCH*XSPLIT), 256, TN_SMEM3_128>>>(
      p_ut, x_proj_w, p_dbcp, SEQ, DBC_W, DINNER, SEQ, DINNER*SEQ, SEQ*DBC_W, XSPLIT);
  // 3b. reduce partials
  reduce_dbc<<<(BATCH*SEQ*DBC_W/4 + 255)/256, 256>>>();
  // 4. delta
  delta_mma<<<dim3(SEQ/64, DINNER/128, BATCH), 256>>>(dt_proj_w, p_dbc, dt_proj_b, p_deltat);
  // 5. scan
  scan_kernel<<<NROWS/8, 256>>>(Dw, A_log);
  // 6. y2 = y @ out_proj_w^T
  gemm_tn<64,2><<<dim3(DMODEL/128, SEQ/64, BATCH), 256, TN_SMEM3_64>>>(
      p_yt, out_proj_w, p_y2, SEQ, DMODEL, DINNER, SEQ, DINNER*SEQ, SEQ*DMODEL, 1);
  // 7. layernorm
  ln_kernel<<<NROWS, 128>>>(ln_w, ln_b);
  // 8. out = gelu(yn @ lin_w^T + lin_b) + residual
  gemm_nt<<<dim3(DMODEL/128, NROWS/128), 256, NT_SMEM3>>>(
      p_yn, lin_w, out, NROWS, DMODEL, DMODEL, 0, 1, lin_b, tokens);
}

// round 14
// speedup vs baseline: 1.1867x; 1.1072x over previous
#include <cuda_runtime.h>
#include <cuda_fp16.h>
#include <cstdint>
#include <math.h>

#define BATCH  4
#define SEQ    1024
#define DMODEL 512
#define DINNER 1024
#define DSTATE 32
#define DTRANK 32
#define DBC_W  96
#define NROWS  (BATCH*SEQ)   // 4096
#define XSPLIT 4

// ================= scratch =================
__device__ float  g_xz    [BATCH*SEQ*2*DINNER];
__device__ float  g_ut    [BATCH*DINNER*SEQ];
__device__ float  g_zt    [BATCH*DINNER*SEQ];
__device__ float  g_dbcp  [XSPLIT*BATCH*SEQ*DBC_W];
__device__ float  g_dbc   [BATCH*SEQ*DBC_W];
__device__ float  g_deltat[BATCH*DINNER*SEQ];
__device__ float  g_yt    [BATCH*DINNER*SEQ];
__device__ float  g_y2    [BATCH*SEQ*DMODEL];
__device__ float  g_yn    [BATCH*SEQ*DMODEL];
__device__ __half g_ah    [NROWS*DMODEL];        // permuted tokens, fp16
__device__ __half g_bh    [2*DINNER*DMODEL];     // in_proj_w, fp16

__device__ __forceinline__ int perm_src(int p) {
  int r = p >> 5, c = p & 31;
  if (r & 1) c = 31 - c;
  return (r << 5) | c;
}
__device__ __forceinline__ int remap_row(int m) {
  return (m & ~(SEQ - 1)) + perm_src(m & (SEQ - 1));
}
__device__ __forceinline__ float softplusf(float x) {
  return fmaxf(x, 0.f) + __logf(1.f + __expf(-fabsf(x)));
}
__device__ __forceinline__ float siluf(float x) {
  return __fdividef(x, 1.f + __expf(-x));
}
__device__ __forceinline__ float fast_erff(float x) {
  float ax = fabsf(x);
  float t = __frcp_rn(fmaf(0.3275911f, ax, 1.f));
  float p = t * fmaf(t, fmaf(t, fmaf(t, fmaf(t, 1.061405429f, -1.453152027f),
                     1.421413741f), -0.284496736f), 0.254829592f);
  float r = 1.f - p * __expf(-ax * ax);
  return copysignf(r, x);
}
__device__ __forceinline__ float geluf(float x) {
  return 0.5f * x * (1.f + fast_erff(x * 0.70710678118654752f));
}
__device__ __forceinline__ uint32_t smem_u32(const void* p) {
  uint32_t a;
  asm("{ .reg .u64 t; cvta.to.shared.u64 t, %1; cvt.u32.u64 %0, t; }" : "=r"(a) : "l"(p));
  return a;
}
__device__ __forceinline__ void cp16(void* dst, const void* src) {
  asm volatile("cp.async.cg.shared.global [%0], [%1], 16;"
               :: "r"(smem_u32(dst)), "l"(src));
}
__device__ __forceinline__ void cp16z(void* dst, const void* src, bool valid) {
  int sz = valid ? 16 : 0;
  asm volatile("cp.async.cg.shared.global [%0], [%1], 16, %2;"
               :: "r"(smem_u32(dst)), "l"(src), "r"(sz));
}
#define CP_COMMIT() asm volatile("cp.async.commit_group;" ::: "memory")
#define CP_WAIT1()  asm volatile("cp.async.wait_group 1;" ::: "memory")
#define CP_WAIT0()  asm volatile("cp.async.wait_group 0;" ::: "memory")

#define LDSM4(r0, r1, r2, r3, addr) \
  asm volatile("ldmatrix.sync.aligned.m8n8.x4.shared.b16 {%0,%1,%2,%3}, [%4];" \
    : "=r"(r0), "=r"(r1), "=r"(r2), "=r"(r3) : "r"(addr))

__device__ __forceinline__ void mma_tf32(float* c, const uint32_t* a, const uint32_t* b) {
  asm volatile(
    "mma.sync.aligned.m16n8k8.row.col.f32.tf32.tf32.f32 "
    "{%0,%1,%2,%3}, {%4,%5,%6,%7}, {%8,%9}, {%0,%1,%2,%3};"
    : "+f"(c[0]), "+f"(c[1]), "+f"(c[2]), "+f"(c[3])
    : "r"(a[0]), "r"(a[1]), "r"(a[2]), "r"(a[3]), "r"(b[0]), "r"(b[1]));
}
__device__ __forceinline__ void mma_f16(float* c, const uint32_t* a, const uint32_t* b) {
  asm volatile(
    "mma.sync.aligned.m16n8k16.row.col.f32.f16.f16.f32 "
    "{%0,%1,%2,%3}, {%4,%5,%6,%7}, {%8,%9}, {%0,%1,%2,%3};"
    : "+f"(c[0]), "+f"(c[1]), "+f"(c[2]), "+f"(c[3])
    : "r"(a[0]), "r"(a[1]), "r"(a[2]), "r"(a[3]), "r"(b[0]), "r"(b[1]));
}

// ================= fp32->fp16 converters =================
__global__ void tok2h(const float* __restrict__ tokens) {
  int i = blockIdx.x * 256 + threadIdx.x;          // 0 .. 4096*512/4
  int row = i >> 7, c4 = (i & 127) * 4;
  float4 v = *(const float4*)&tokens[(size_t)remap_row(row) * DMODEL + c4];
  __half2* dst = (__half2*)&g_ah[(size_t)row * DMODEL + c4];
  dst[0] = __floats2half2_rn(v.x, v.y);
  dst[1] = __floats2half2_rn(v.z, v.w);
}
__global__ void w2h(const float* __restrict__ w) {
  int i = blockIdx.x * 256 + threadIdx.x;          // 0 .. 2048*512/4
  float4 v = *(const float4*)&w[(size_t)i * 4];
  __half2* dst = (__half2*)&g_bh[(size_t)i * 4];
  dst[0] = __floats2half2_rn(v.x, v.y);
  dst[1] = __floats2half2_rn(v.z, v.w);
}

// ================= fp16 GEMM NT for in_proj ==================
// C[M,N] = A[M,K] @ B[N,K]^T, A/B fp16 row-major, C fp32. k-chunk 64 (128B rows).
// Smem 16B-chunk c of row r at (c ^ (r&7)) — identical swizzle to fp32 kernels.
#define F16_STAGE_B (2*128*128)            // bytes per stage (A tile + B tile)
#define F16_SMEM3   (3*F16_STAGE_B)        // 98304 B
__global__ __launch_bounds__(256, 2) void gemm_f16_nt(const __half* __restrict__ A,
    const __half* __restrict__ B, float* __restrict__ C, int M, int N, int K) {
  extern __shared__ char smc[];
  const uint32_t sbase = smem_u32(smc);
  const int tid = threadIdx.x;
  const int wid = tid >> 5, lane = tid & 31;
  const int wm = wid & 3, wn = wid >> 2;
  const int group = lane >> 2, tg = lane & 3;
  const int m0 = blockIdx.y * 128, n0 = blockIdx.x * 128;
  const int lr = tid >> 3, lk = tid & 7;
  const int KC = K / 64;

  int a_row[2], b_row[4];
#pragma unroll
  for (int i = 0; i < 2; i++)
    a_row[i] = wm * 32 + i * 16 + (lane & 7) + ((lane & 8) ? 8 : 0);
#pragma unroll
  for (int j2 = 0; j2 < 4; j2++)
    b_row[j2] = wn * 64 + j2 * 16 + (lane & 7) + ((lane & 16) ? 8 : 0);
  const int a_qc = (lane & 16) ? 1 : 0;
  const int b_qc = (lane & 8) ? 1 : 0;

  float acc[2][8][4] = {};

#define F16_LOAD(c) do { \
    int k0 = (c) * 64; \
    char* st = smc + ((c) % 3) * F16_STAGE_B; \
    _Pragma("unroll") \
    for (int pass = 0; pass < 4; ++pass) { \
      int r = lr + pass * 32; \
      int sc = (lk ^ (r & 7)) * 16; \
      cp16(st + r * 128 + sc, &A[(size_t)(m0 + r) * K + k0 + lk * 8]); \
      cp16(st + 128 * 128 + r * 128 + sc, &B[(size_t)(n0 + r) * K + k0 + lk * 8]); \
    } \
    CP_COMMIT(); \
  } while (0)

  F16_LOAD(0);
  if (KC > 1) F16_LOAD(1);
  for (int c = 0; c < KC; ++c) {
    if (c + 1 < KC) CP_WAIT1(); else CP_WAIT0();
    __syncthreads();
    if (c + 2 < KC) F16_LOAD(c + 2);
    const uint32_t stA = sbase + (c % 3) * F16_STAGE_B;
    const uint32_t stB = stA + 128 * 128;
#pragma unroll
    for (int ks = 0; ks < 4; ++ks) {
      uint32_t af[2][4], bfr[8][2];
#pragma unroll
      for (int i = 0; i < 2; i++) {
        uint32_t ad = stA + a_row[i] * 128 + ((((2 * ks + a_qc) ^ (a_row[i] & 7))) << 4);
        LDSM4(af[i][0], af[i][1], af[i][2], af[i][3], ad);
      }
#pragma unroll
      for (int j2 = 0; j2 < 4; j2++) {
        uint32_t bd = stB + b_row[j2] * 128 + ((((2 * ks + b_qc) ^ (b_row[j2] & 7))) << 4);
        uint32_t r0, r1, r2, r3;
        LDSM4(r0, r1, r2, r3, bd);
        bfr[2*j2][0] = r0; bfr[2*j2][1] = r1;
        bfr[2*j2+1][0] = r2; bfr[2*j2+1][1] = r3;
      }
#pragma unroll
      for (int i = 0; i < 2; i++)
#pragma unroll
        for (int j = 0; j < 8; j++)
          mma_f16(acc[i][j], af[i], bfr[j]);
    }
  }
#undef F16_LOAD
#pragma unroll
  for (int i = 0; i < 2; i++) {
    int row0 = m0 + wm * 32 + i * 16 + group;
#pragma unroll
    for (int j = 0; j < 8; j++) {
      int col = n0 + wn * 64 + j * 8 + tg * 2;
      *(float2*)&C[(size_t)row0 * N + col]       = make_float2(acc[i][j][0], acc[i][j][1]);
      *(float2*)&C[(size_t)(row0 + 8) * N + col] = make_float2(acc[i][j][2], acc[i][j][3]);
    }
  }
}

// ================= fp32/tf32 GEMM NT (R8; used for lin with fused epilogue) ======
#define NT_STAGE (2*128*32)
#define NT_SMEM3 (3*NT_STAGE*4)
__global__ __launch_bounds__(256, 2) void gemm_nt(const float* __restrict__ A,
    const float* __restrict__ B, float* __restrict__ C, int M, int N, int K,
    int gatherA, int epi, const float* __restrict__ bias,
    const float* __restrict__ resid) {
  extern __shared__ float sm[];
  const uint32_t sbase = smem_u32(sm);
  const int tid = threadIdx.x;
  const int wid = tid >> 5, lane = tid & 31;
  const int wm = wid & 3, wn = wid >> 2;
  const int group = lane >> 2, tg = lane & 3;
  const int m0 = blockIdx.y * 128, n0 = blockIdx.x * 128;
  const int lr = tid >> 3, lk = tid & 7;
  const int KC = K / 32;

  int a_row[2], b_row[4];
#pragma unroll
  for (int i = 0; i < 2; i++)
    a_row[i] = wm * 32 + i * 16 + (lane & 7) + ((lane & 8) ? 8 : 0);
#pragma unroll
  for (int j2 = 0; j2 < 4; j2++)
    b_row[j2] = wn * 64 + j2 * 16 + (lane & 7) + ((lane & 16) ? 8 : 0);
  const int a_qc = (lane & 16) ? 1 : 0;
  const int b_qc = (lane & 8) ? 1 : 0;

  float acc[2][8][4] = {};

  int arow[4];
#pragma unroll
  for (int pass = 0; pass < 4; ++pass) {
    int m = m0 + lr + pass * 32;
    arow[pass] = gatherA ? remap_row(m) : m;
  }

#define NT_LOAD(c) do { \
    int k0 = (c) * 32; \
    float* st = sm + ((c) % 3) * NT_STAGE; \
    _Pragma("unroll") \
    for (int pass = 0; pass < 4; ++pass) { \
      int r = lr + pass * 32; \
      int sc = (lk ^ (r & 7)) * 4; \
      cp16(st + r * 32 + sc, &A[(size_t)arow[pass] * K + k0 + lk * 4]); \
      cp16(st + 128 * 32 + r * 32 + sc, &B[(size_t)(n0 + r) * K + k0 + lk * 4]); \
    } \
    CP_COMMIT(); \
  } while (0)

  NT_LOAD(0);
  if (KC > 1) NT_LOAD(1);
  for (int c = 0; c < KC; ++c) {
    if (c + 1 < KC) CP_WAIT1(); else CP_WAIT0();
    __syncthreads();
    if (c + 2 < KC) NT_LOAD(c + 2);
    const uint32_t stA = sbase + ((c % 3) * NT_STAGE) * 4;
    const uint32_t stB = stA + 128 * 32 * 4;
#pragma unroll
    for (int ks = 0; ks < 4; ++ks) {
      uint32_t af[2][4], bfr[8][2];
#pragma unroll
      for (int i = 0; i < 2; i++) {
        uint32_t ad = stA + a_row[i] * 128 + ((((2 * ks + a_qc) ^ (a_row[i] & 7))) << 4);
        LDSM4(af[i][0], af[i][1], af[i][2], af[i][3], ad);
      }
#pragma unroll
      for (int j2 = 0; j2 < 4; j2++) {
        uint32_t bd = stB + b_row[j2] * 128 + ((((2 * ks + b_qc) ^ (b_row[j2] & 7))) << 4);
        uint32_t r0, r1, r2, r3;
        LDSM4(r0, r1, r2, r3, bd);
        bfr[2*j2][0] = r0; bfr[2*j2][1] = r1;
        bfr[2*j2+1][0] = r2; bfr[2*j2+1][1] = r3;
      }
#pragma unroll
      for (int i = 0; i < 2; i++)
#pragma unroll
        for (int j = 0; j < 8; j++)
          mma_tf32(acc[i][j], af[i], bfr[j]);
    }
  }
#undef NT_LOAD
  if (epi == 0) {
#pragma unroll
    for (int i = 0; i < 2; i++) {
      int row0 = m0 + wm * 32 + i * 16 + group;
#pragma unroll
      for (int j = 0; j < 8; j++) {
        int col = n0 + wn * 64 + j * 8 + tg * 2;
        *(float2*)&C[(size_t)row0 * N + col]       = make_float2(acc[i][j][0], acc[i][j][1]);
        *(float2*)&C[(size_t)(row0 + 8) * N + col] = make_float2(acc[i][j][2], acc[i][j][3]);
      }
    }
  } else {
#pragma unroll
    for (int i = 0; i < 2; i++) {
      int row0 = m0 + wm * 32 + i * 16 + group;
      int ra = remap_row(row0), rb = remap_row(row0 + 8);
#pragma unroll
      for (int j = 0; j < 8; j++) {
        int col = n0 + wn * 64 + j * 8 + tg * 2;
        float b0 = bias[col], b1 = bias[col + 1];
        size_t oa = (size_t)ra * N + col, ob = (size_t)rb * N + col;
        float2 r0 = *(const float2*)&resid[oa];
        float2 r1 = *(const float2*)&resid[ob];
        *(float2*)&C[oa] = make_float2(geluf(acc[i][j][0] + b0) + r0.x,
                                       geluf(acc[i][j][1] + b1) + r0.y);
        *(float2*)&C[ob] = make_float2(geluf(acc[i][j][2] + b0) + r1.x,
                                       geluf(acc[i][j][3] + b1) + r1.y);
      }
    }
  }
}

// ================= GEMM TN (R8) =================
template<int MT, int WMW>
__global__ __launch_bounds__(256, 2) void gemm_tn(const float* __restrict__ At,
    const float* __restrict__ B, float* __restrict__ C, int M, int N, int K,
    int lda, int sA, int sC, int nsplit) {
  constexpr int WNW = 8 / WMW;
  constexpr int WNT = 128 / WNW;
  constexpr int JF  = WNT / 8;
  constexpr int JF2 = JF / 2;
  constexpr int AST = MT + 8;
  constexpr int STG = 32 * AST + 128 * 32;
  const int z = blockIdx.z;
  const int b = z / nsplit, s = z - b * nsplit;
  const int Kp = K / nsplit;
  At += (size_t)b * sA + (size_t)(s * Kp) * lda;
  C  += (size_t)z * sC;
  extern __shared__ float sm[];
  const uint32_t sbase = smem_u32(sm);
  const int tid = threadIdx.x;
  const int wid = tid >> 5, lane = tid & 31;
  const int wm = wid % WMW, wn = wid / WMW;
  const int group = lane >> 2, tg = lane & 3;
  const int m0 = blockIdx.y * MT, n0 = blockIdx.x * 128;
  const int lr = tid >> 3, lk = tid & 7;
  const int akk = tid >> 3, amc = tid & 7;
  const int KC = Kp / 32;

  int b_row[JF2];
#pragma unroll
  for (int j2 = 0; j2 < JF2; j2++)
    b_row[j2] = wn * WNT + j2 * 16 + (lane & 7) + ((lane & 16) ? 8 : 0);
  const int b_qc = (lane & 8) ? 1 : 0;

  float acc[2][JF][4] = {};

#define TN_LOAD(c) do { \
    int k0 = (c) * 32; \
    float* stA_ = sm + ((c) % 3) * STG; \
    float* stB_ = stA_ + 32 * AST; \
    _Pragma("unroll") \
    for (int pass = 0; pass < MT/32; ++pass) { \
      int mc = amc + pass * 8; \
      cp16(stA_ + akk * AST + mc * 4, &At[(size_t)(k0 + akk) * lda + m0 + mc * 4]); \
    } \
    _Pragma("unroll") \
    for (int pass = 0; pass < 4; ++pass) { \
      int r = lr + pass * 32; \
      int sc = (lk ^ (r & 7)) * 4; \
      cp16z(stB_ + r * 32 + sc, &B[(size_t)(n0 + r) * K + s * Kp + k0 + lk * 4], n0 + r < N); \
    } \
    CP_COMMIT(); \
  } while (0)

  TN_LOAD(0);
  if (KC > 1) TN_LOAD(1);
  for (int c = 0; c < KC; ++c) {
    if (c + 1 < KC) CP_WAIT1(); else CP_WAIT0();
    __syncthreads();
    if (c + 2 < KC) TN_LOAD(c + 2);
    float (*Asr)[AST] = (float(*)[AST])(sm + (c % 3) * STG);
    const uint32_t stB = sbase + ((c % 3) * STG + 32 * AST) * 4;
#pragma unroll
    for (int ks = 0; ks < 4; ++ks) {
      int kk = ks * 8;
      uint32_t af[2][4], bfr[JF][2];
#pragma unroll
      for (int i = 0; i < 2; i++) {
        int mr = wm * 32 + i * 16;
        af[i][0] = __float_as_uint(Asr[kk + tg    ][mr + group    ]);
        af[i][1] = __float_as_uint(Asr[kk + tg    ][mr + group + 8]);
        af[i][2] = __float_as_uint(Asr[kk + tg + 4][mr + group    ]);
        af[i][3] = __float_as_uint(Asr[kk + tg + 4][mr + group + 8]);
      }
#pragma unroll
      for (int j2 = 0; j2 < JF2; j2++) {
        uint32_t bd = stB + b_row[j2] * 128 + ((((2 * ks + b_qc) ^ (b_row[j2] & 7))) << 4);
        uint32_t r0, r1, r2, r3;
        LDSM4(r0, r1, r2, r3, bd);
        bfr[2*j2][0] = r0; bfr[2*j2][1] = r1;
        bfr[2*j2+1][0] = r2; bfr[2*j2+1][1] = r3;
      }
#pragma unroll
      for (int i = 0; i < 2; i++)
#pragma unroll
        for (int j = 0; j < JF; j++)
          mma_tf32(acc[i][j], af[i], bfr[j]);
    }
  }
#undef TN_LOAD
#pragma unroll
  for (int i = 0; i < 2; i++) {
    int row0 = m0 + wm * 32 + i * 16 + group;
#pragma unroll
    for (int j = 0; j < JF; j++) {
      int col = n0 + wn * WNT + j * 8 + tg * 2;
      if (col < N) {
        *(float2*)&C[(size_t)row0 * N + col]       = make_float2(acc[i][j][0], acc[i][j][1]);
        *(float2*)&C[(size_t)(row0 + 8) * N + col] = make_float2(acc[i][j][2], acc[i][j][3]);
      }
    }
  }
}
#define TN_SMEM3_128 (3*(32*136 + 128*32)*4)
#define TN_SMEM3_64  (3*(32*72  + 128*32)*4)

// ================= split-K reduce for dbc =================
__global__ void reduce_dbc() {
  int i = blockIdx.x * 256 + threadIdx.x;
  const int per = BATCH*SEQ*DBC_W/4;
  if (i >= per) return;
  const float4* p = (const float4*)g_dbcp;
  int b = i / (SEQ*DBC_W/4);
  int off = i - b * (SEQ*DBC_W/4);
  float4 r = make_float4(0.f,0.f,0.f,0.f);
#pragma unroll
  for (int s = 0; s < XSPLIT; s++) {
    float4 v = p[(size_t)(b*XSPLIT + s) * (SEQ*DBC_W/4) + off];
    r.x += v.x; r.y += v.y; r.z += v.z; r.w += v.w;
  }
  ((float4*)g_dbc)[i] = r;
}

// ================= delta via mma (R8) =================
__global__ __launch_bounds__(256) void delta_mma(const float* __restrict__ W,
    const float* __restrict__ dbc, const float* __restrict__ bias,
    float* __restrict__ outp) {
  __shared__ float As[128][36];
  __shared__ float Bs[64][36];
  const int b = blockIdx.z;
  const int tid = threadIdx.x;
  const int wid = tid >> 5, lane = tid & 31;
  const int wm = wid & 3, wn = wid >> 2;
  const int group = lane >> 2, tg = lane & 3;
  const int m0 = blockIdx.y * 128, n0 = blockIdx.x * 64;

  const float* Bb = dbc + (size_t)b * SEQ * DBC_W;
#pragma unroll
  for (int pass = 0; pass < 4; ++pass) {
    int i = tid + pass * 256;
    int r = i >> 3, q = i & 7;
    *(float4*)&As[r][q * 4] = *(const float4*)&W[(size_t)(m0 + r) * DTRANK + q * 4];
  }
#pragma unroll
  for (int pass = 0; pass < 2; ++pass) {
    int i = tid + pass * 256;
    int r = i >> 3, q = i & 7;
    *(float4*)&Bs[r][q * 4] = *(const float4*)&Bb[(size_t)(n0 + r) * DBC_W + q * 4];
  }
  __syncthreads();

  float acc[2][4][4] = {};
#pragma unroll
  for (int ks = 0; ks < 4; ++ks) {
    int kk = ks * 8;
    uint32_t af[2][4], bfr[4][2];
#pragma unroll
    for (int i = 0; i < 2; i++) {
      int mr = wm * 32 + i * 16;
      af[i][0] = __float_as_uint(As[mr + group    ][kk + tg    ]);
      af[i][1] = __float_as_uint(As[mr + group + 8][kk + tg    ]);
      af[i][2] = __float_as_uint(As[mr + group    ][kk + tg + 4]);
      af[i][3] = __float_as_uint(As[mr + group + 8][kk + tg + 4]);
    }
#pragma unroll
    for (int j = 0; j < 4; j++) {
      int nr = wn * 32 + j * 8;
      bfr[j][0] = __float_as_uint(Bs[nr + group][kk + tg    ]);
      bfr[j][1] = __float_as_uint(Bs[nr + group][kk + tg + 4]);
    }
#pragma unroll
    for (int i = 0; i < 2; i++)
#pragma unroll
      for (int j = 0; j < 4; j++)
        mma_tf32(acc[i][j], af[i], bfr[j]);
  }
  float* ob = outp + (size_t)b * DINNER * SEQ;
#pragma unroll
  for (int i = 0; i < 2; i++) {
    int d0 = m0 + wm * 32 + i * 16 + group;
    float ba = bias[d0], bb2 = bias[d0 + 8];
#pragma unroll
    for (int j = 0; j < 4; j++) {
      int t = n0 + wn * 32 + j * 8 + tg * 2;
      *(float2*)&ob[(size_t)d0 * SEQ + t] =
        make_float2(softplusf(acc[i][j][0] + ba), softplusf(acc[i][j][1] + ba));
      *(float2*)&ob[(size_t)(d0 + 8) * SEQ + t] =
        make_float2(softplusf(acc[i][j][2] + bb2), softplusf(acc[i][j][3] + bb2));
    }
  }
}

// ================= conv + silu + z-silu, transposed to [b,d,t] (R8) =============
__global__ void convz_kernel(const float* __restrict__ conv_w, const float* __restrict__ conv_b) {
  __shared__ float sx[67][33];
  __shared__ float sz[64][33];
  int b = blockIdx.z, t0 = blockIdx.x * 64, d0 = blockIdx.y * 32;
  int tid = threadIdx.y * 64 + threadIdx.x;
  for (int i = tid; i < 67*32; i += 256) {
    int r = i >> 5, c = i & 31;
    int t = t0 - 3 + r;
    sx[r][c] = (t >= 0) ? g_xz[(size_t)(b*SEQ + t)*2*DINNER + d0 + c] : 0.f;
  }
  for (int i = tid; i < 64*32; i += 256) {
    int r = i >> 5, c = i & 31;
    sz[r][c] = g_xz[(size_t)(b*SEQ + t0 + r)*2*DINNER + DINNER + d0 + c];
  }
  __syncthreads();
  int tx = threadIdx.x;
#pragma unroll
  for (int i = 0; i < 8; i++) {
    int dl = threadIdx.y * 8 + i;
    int d = d0 + dl;
    float w0 = conv_w[d*4+0], w1 = conv_w[d*4+1], w2 = conv_w[d*4+2], w3 = conv_w[d*4+3];
    float acc = conv_b[d];
    acc += sx[tx+0][dl]*w0 + sx[tx+1][dl]*w1 + sx[tx+2][dl]*w2 + sx[tx+3][dl]*w3;
    size_t o = (size_t)(b*DINNER + d)*SEQ + t0 + tx;
    g_ut[o] = siluf(acc);
    g_zt[o] = siluf(sz[tx][dl]);
  }
}

// ================= selective scan (R8) =================
__global__ void scan_kernel(const float* __restrict__ Dw, const float* __restrict__ A_log) {
  int warp = threadIdx.x >> 5, lane = threadIdx.x & 31;
  int g = blockIdx.x * 8 + warp;
  int b = g >> 10, d = g & 1023;
  __shared__ float sBC[32][64];
  __shared__ float sP[8][32][34];
  float An = -__expf(A_log[d*DSTATE + lane]);
  float Dd = Dw[d];
  float h = 0.f;
  const float* ut  = g_ut     + (size_t)(b*DINNER + d)*SEQ;
  const float* dtp = g_deltat + (size_t)(b*DINNER + d)*SEQ;
  const float* ztp = g_zt     + (size_t)(b*DINNER + d)*SEQ;
  float*       ytp = g_yt     + (size_t)(b*DINNER + d)*SEQ;

  for (int t0 = 0; t0 < SEQ; t0 += 32) {
    __syncthreads();
    for (int i = threadIdx.x; i < 32*64; i += 256) {
      int s = i >> 6, c = i & 63;
      sBC[s][c] = g_dbc[(size_t)(b*SEQ + t0 + s)*DBC_W + DSTATE + c];
    }
    __syncthreads();
    float du = ut[t0 + lane];
    float dd = dtp[t0 + lane];
    float sz = ztp[t0 + lane];
#pragma unroll 8
    for (int s = 0; s < 32; s++) {
      float delta_t = __shfl_sync(0xffffffffu, dd, s);
      float u_t     = __shfl_sync(0xffffffffu, du, s);
      float dA = __expf(delta_t * An);
      h = fmaf(dA, h, delta_t * u_t * sBC[s][lane]);
      sP[warp][s][lane] = h * sBC[s][32 + lane];
    }
    __syncwarp();
    float y = du * Dd;
#pragma unroll
    for (int i = 0; i < 32; i++) {
      int c = (lane + i) & 31;
      y += sP[warp][lane][c];
    }
    ytp[t0 + lane] = y * sz;
  }
}

// ================= layernorm (R8) =================
__global__ void ln_kernel(const float* __restrict__ lnw, const float* __restrict__ lnb) {
  int row = blockIdx.x;
  const float* y = g_y2 + (size_t)row * DMODEL;
  float*       o = g_yn + (size_t)row * DMODEL;
  int tid = threadIdx.x;
  int lane = tid & 31, wid = tid >> 5;
  float v[4], s = 0.f, s2 = 0.f;
#pragma unroll
  for (int i = 0; i < 4; i++) {
    float x = y[tid + i*128];
    v[i] = x; s += x; s2 += x*x;
  }
#pragma unroll
  for (int off = 16; off >= 1; off >>= 1) {
    s  += __shfl_xor_sync(0xffffffffu, s, off);
    s2 += __shfl_xor_sync(0xffffffffu, s2, off);
  }
  __shared__ float sh[10];
  if (lane == 0) { sh[wid] = s; sh[4 + wid] = s2; }
  __syncthreads();
  if (tid == 0) {
    float ts = sh[0] + sh[1] + sh[2] + sh[3];
    float ts2 = sh[4] + sh[5] + sh[6] + sh[7];
    float mu = ts * (1.f/DMODEL);
    float var = ts2 * (1.f/DMODEL) - mu*mu;
    sh[8] = mu;
    sh[9] = rsqrtf(var + 1e-5f);
  }
  __syncthreads();
  float mu = sh[8], inv = sh[9];
#pragma unroll
  for (int i = 0; i < 4; i++) {
    int c = tid + i*128;
    o[c] = (v[i] - mu) * inv * lnw[c] + lnb[c];
  }
}

// ================= launch =================
extern "C" void kernel_launch(void* const* d_in, const int* in_sizes, int n_in,
                              void* d_out, int out_size) {
  const float* tokens     = (const float*)d_in[0];
  const float* in_proj_w  = (const float*)d_in[1];
  const float* conv_w     = (const float*)d_in[2];
  const float* conv_b     = (const float*)d_in[3];
  const float* x_proj_w   = (const float*)d_in[4];
  const float* dt_proj_w  = (const float*)d_in[5];
  const float* dt_proj_b  = (const float*)d_in[6];
  const float* A_log      = (const float*)d_in[7];
  const float* Dw         = (const float*)d_in[8];
  const float* out_proj_w = (const float*)d_in[9];
  const float* ln_w       = (const float*)d_in[10];
  const float* ln_b       = (const float*)d_in[11];
  const float* lin_w      = (const float*)d_in[12];
  const float* lin_b      = (const float*)d_in[13];
  float* out = (float*)d_out;

  float *p_xz, *p_ut, *p_dbcp, *p_dbc, *p_deltat, *p_yt, *p_y2, *p_yn;
  __half *p_ah, *p_bh;
  cudaGetSymbolAddress((void**)&p_xz,     g_xz);
  cudaGetSymbolAddress((void**)&p_ut,     g_ut);
  cudaGetSymbolAddress((void**)&p_dbcp,   g_dbcp);
  cudaGetSymbolAddress((void**)&p_dbc,    g_dbc);
  cudaGetSymbolAddress((void**)&p_deltat, g_deltat);
  cudaGetSymbolAddress((void**)&p_yt,     g_yt);
  cudaGetSymbolAddress((void**)&p_y2,     g_y2);
  cudaGetSymbolAddress((void**)&p_yn,     g_yn);
  cudaGetSymbolAddress((void**)&p_ah,     g_ah);
  cudaGetSymbolAddress((void**)&p_bh,     g_bh);

  cudaFuncSetAttribute(gemm_nt, cudaFuncAttributeMaxDynamicSharedMemorySize, NT_SMEM3);
  cudaFuncSetAttribute(gemm_f16_nt, cudaFuncAttributeMaxDynamicSharedMemorySize, F16_SMEM3);
  cudaFuncSetAttribute(gemm_tn<128,4>, cudaFuncAttributeMaxDynamicSharedMemorySize, TN_SMEM3_128);
  cudaFuncSetAttribute(gemm_tn<64,2>,  cudaFuncAttributeMaxDynamicSharedMemorySize, TN_SMEM3_64);

  // 0. fp16 conversions (permutation fused into token convert)
  tok2h<<<NROWS*DMODEL/4/256, 256>>>(tokens);
  w2h<<<2*DINNER*DMODEL/4/256, 256>>>(in_proj_w);
  // 1. xz = ah @ bh^T  (fp16 tensor cores)
  gemm_f16_nt<<<dim3(2*DINNER/128, NROWS/128), 256, F16_SMEM3>>>(
      p_ah, p_bh, p_xz, NROWS, 2*DINNER, DMODEL);
  // 2. conv+silu -> ut ; silu(z) -> zt
  convz_kernel<<<dim3(SEQ/64, DINNER/32, BATCH), dim3(64,4)>>>(conv_w, conv_b);
  // 3. dbc partials (split-K=4)
  gemm_tn<128,4><<<dim3(1, SEQ/128, BATCH*XSPLIT), 256, TN_SMEM3_128>>>(
      p_ut, x_proj_w, p_dbcp, SEQ, DBC_W, DINNER, SEQ, DINNER*SEQ, SEQ*DBC_W, XSPLIT);
  // 3b. reduce partials
  reduce_dbc<<<(BATCH*SEQ*DBC_W/4 + 255)/256, 256>>>();
  // 4. delta
  delta_mma<<<dim3(SEQ/64, DINNER/128, BATCH), 256>>>(dt_proj_w, p_dbc, dt_proj_b, p_deltat);
  // 5. scan
  scan_kernel<<<NROWS/8, 256>>>(Dw, A_log);
  // 6. y2 = y @ out_proj_w^T
  gemm_tn<64,2><<<dim3(DMODEL/128, SEQ/64, BATCH), 256, TN_SMEM3_64>>>(
      p_yt, out_proj_w, p_y2, SEQ, DMODEL, DINNER, SEQ, DINNER*SEQ, SEQ*DMODEL, 1);
  // 7. layernorm
  ln_kernel<<<NROWS, 128>>>(ln_w, ln_b);
  // 8. out = gelu(yn @ lin_w^T + lin_b) + residual
  gemm_nt<<<dim3(DMODEL/128, NROWS/128), 256, NT_SMEM3>>>(
      p_yn, lin_w, out, NROWS, DMODEL, DMODEL, 0, 1, lin_b, tokens);
}

// round 15
// speedup vs baseline: 1.1937x; 1.0059x over previous
#include <cuda_runtime.h>
#include <cuda_fp16.h>
#include <cstdint>
#include <math.h>

#define BATCH  4
#define SEQ    1024
#define DMODEL 512
#define DINNER 1024
#define DSTATE 32
#define DTRANK 32
#define DBC_W  96
#define NROWS  (BATCH*SEQ)   // 4096
#define XSPLIT 4

// ================= scratch =================
__device__ float  g_xz    [BATCH*SEQ*2*DINNER];
__device__ float  g_ut    [BATCH*DINNER*SEQ];
__device__ float  g_zt    [BATCH*DINNER*SEQ];
__device__ float  g_dbcp  [XSPLIT*BATCH*SEQ*DBC_W];
__device__ float  g_dbc   [BATCH*SEQ*DBC_W];
__device__ float  g_deltat[BATCH*DINNER*SEQ];
__device__ float  g_yt    [BATCH*DINNER*SEQ];
__device__ float  g_y2    [BATCH*SEQ*DMODEL];
__device__ __half g_ynh   [BATCH*SEQ*DMODEL];    // layernorm output, fp16
__device__ __half g_ah    [NROWS*DMODEL];        // permuted tokens, fp16
__device__ __half g_bh    [2*DINNER*DMODEL];     // in_proj_w, fp16
__device__ __half g_lwh   [DMODEL*DMODEL];       // lin_w, fp16

__device__ __forceinline__ int perm_src(int p) {
  int r = p >> 5, c = p & 31;
  if (r & 1) c = 31 - c;
  return (r << 5) | c;
}
__device__ __forceinline__ int remap_row(int m) {
  return (m & ~(SEQ - 1)) + perm_src(m & (SEQ - 1));
}
__device__ __forceinline__ float softplusf(float x) {
  return fmaxf(x, 0.f) + __logf(1.f + __expf(-fabsf(x)));
}
__device__ __forceinline__ float siluf(float x) {
  return __fdividef(x, 1.f + __expf(-x));
}
__device__ __forceinline__ float fast_erff(float x) {
  float ax = fabsf(x);
  float t = __frcp_rn(fmaf(0.3275911f, ax, 1.f));
  float p = t * fmaf(t, fmaf(t, fmaf(t, fmaf(t, 1.061405429f, -1.453152027f),
                     1.421413741f), -0.284496736f), 0.254829592f);
  float r = 1.f - p * __expf(-ax * ax);
  return copysignf(r, x);
}
__device__ __forceinline__ float geluf(float x) {
  return 0.5f * x * (1.f + fast_erff(x * 0.70710678118654752f));
}
__device__ __forceinline__ uint32_t smem_u32(const void* p) {
  uint32_t a;
  asm("{ .reg .u64 t; cvta.to.shared.u64 t, %1; cvt.u32.u64 %0, t; }" : "=r"(a) : "l"(p));
  return a;
}
__device__ __forceinline__ void cp16(void* dst, const void* src) {
  asm volatile("cp.async.cg.shared.global [%0], [%1], 16;"
               :: "r"(smem_u32(dst)), "l"(src));
}
__device__ __forceinline__ void cp16z(void* dst, const void* src, bool valid) {
  int sz = valid ? 16 : 0;
  asm volatile("cp.async.cg.shared.global [%0], [%1], 16, %2;"
               :: "r"(smem_u32(dst)), "l"(src), "r"(sz));
}
#define CP_COMMIT() asm volatile("cp.async.commit_group;" ::: "memory")
#define CP_WAIT1()  asm volatile("cp.async.wait_group 1;" ::: "memory")
#define CP_WAIT0()  asm volatile("cp.async.wait_group 0;" ::: "memory")

#define LDSM4(r0, r1, r2, r3, addr) \
  asm volatile("ldmatrix.sync.aligned.m8n8.x4.shared.b16 {%0,%1,%2,%3}, [%4];" \
    : "=r"(r0), "=r"(r1), "=r"(r2), "=r"(r3) : "r"(addr))

__device__ __forceinline__ void mma_tf32(float* c, const uint32_t* a, const uint32_t* b) {
  asm volatile(
    "mma.sync.aligned.m16n8k8.row.col.f32.tf32.tf32.f32 "
    "{%0,%1,%2,%3}, {%4,%5,%6,%7}, {%8,%9}, {%0,%1,%2,%3};"
    : "+f"(c[0]), "+f"(c[1]), "+f"(c[2]), "+f"(c[3])
    : "r"(a[0]), "r"(a[1]), "r"(a[2]), "r"(a[3]), "r"(b[0]), "r"(b[1]));
}
__device__ __forceinline__ void mma_f16(float* c, const uint32_t* a, const uint32_t* b) {
  asm volatile(
    "mma.sync.aligned.m16n8k16.row.col.f32.f16.f16.f32 "
    "{%0,%1,%2,%3}, {%4,%5,%6,%7}, {%8,%9}, {%0,%1,%2,%3};"
    : "+f"(c[0]), "+f"(c[1]), "+f"(c[2]), "+f"(c[3])
    : "r"(a[0]), "r"(a[1]), "r"(a[2]), "r"(a[3]), "r"(b[0]), "r"(b[1]));
}

// ================= fp32->fp16 converters =================
__global__ void tok2h(const float* __restrict__ tokens) {
  int i = blockIdx.x * 256 + threadIdx.x;
  int row = i >> 7, c4 = (i & 127) * 4;
  float4 v = *(const float4*)&tokens[(size_t)remap_row(row) * DMODEL + c4];
  __half2* dst = (__half2*)&g_ah[(size_t)row * DMODEL + c4];
  dst[0] = __floats2half2_rn(v.x, v.y);
  dst[1] = __floats2half2_rn(v.z, v.w);
}
__global__ void w2h(const float* __restrict__ w, __half* __restrict__ o) {
  int i = blockIdx.x * 256 + threadIdx.x;
  float4 v = *(const float4*)&w[(size_t)i * 4];
  __half2* dst = (__half2*)&o[(size_t)i * 4];
  dst[0] = __floats2half2_rn(v.x, v.y);
  dst[1] = __floats2half2_rn(v.z, v.w);
}

// ================= fp16 GEMM NT ==================
// C[M,N] = A[M,K] @ B[N,K]^T, A/B fp16 row-major, C fp32. k-chunk 64 (128B rows).
// epi=0: plain store. epi=1: gelu+bias+residual, rows scattered via remap_row.
#define F16_STAGE_B (2*128*128)
#define F16_SMEM3   (3*F16_STAGE_B)        // 98304 B
__global__ __launch_bounds__(256, 2) void gemm_f16_nt(const __half* __restrict__ A,
    const __half* __restrict__ B, float* __restrict__ C, int M, int N, int K,
    int epi, const float* __restrict__ bias, const float* __restrict__ resid) {
  extern __shared__ char smc[];
  const uint32_t sbase = smem_u32(smc);
  const int tid = threadIdx.x;
  const int wid = tid >> 5, lane = tid & 31;
  const int wm = wid & 3, wn = wid >> 2;
  const int group = lane >> 2, tg = lane & 3;
  const int m0 = blockIdx.y * 128, n0 = blockIdx.x * 128;
  const int lr = tid >> 3, lk = tid & 7;
  const int KC = K / 64;

  int a_row[2], b_row[4];
#pragma unroll
  for (int i = 0; i < 2; i++)
    a_row[i] = wm * 32 + i * 16 + (lane & 7) + ((lane & 8) ? 8 : 0);
#pragma unroll
  for (int j2 = 0; j2 < 4; j2++)
    b_row[j2] = wn * 64 + j2 * 16 + (lane & 7) + ((lane & 16) ? 8 : 0);
  const int a_qc = (lane & 16) ? 1 : 0;
  const int b_qc = (lane & 8) ? 1 : 0;

  float acc[2][8][4] = {};

#define F16_LOAD(c) do { \
    int k0 = (c) * 64; \
    char* st = smc + ((c) % 3) * F16_STAGE_B; \
    _Pragma("unroll") \
    for (int pass = 0; pass < 4; ++pass) { \
      int r = lr + pass * 32; \
      int sc = (lk ^ (r & 7)) * 16; \
      cp16(st + r * 128 + sc, &A[(size_t)(m0 + r) * K + k0 + lk * 8]); \
      cp16(st + 128 * 128 + r * 128 + sc, &B[(size_t)(n0 + r) * K + k0 + lk * 8]); \
    } \
    CP_COMMIT(); \
  } while (0)

  F16_LOAD(0);
  if (KC > 1) F16_LOAD(1);
  for (int c = 0; c < KC; ++c) {
    if (c + 1 < KC) CP_WAIT1(); else CP_WAIT0();
    __syncthreads();
    if (c + 2 < KC) F16_LOAD(c + 2);
    const uint32_t stA = sbase + (c % 3) * F16_STAGE_B;
    const uint32_t stB = stA + 128 * 128;
#pragma unroll
    for (int ks = 0; ks < 4; ++ks) {
      uint32_t af[2][4], bfr[8][2];
#pragma unroll
      for (int i = 0; i < 2; i++) {
        uint32_t ad = stA + a_row[i] * 128 + ((((2 * ks + a_qc) ^ (a_row[i] & 7))) << 4);
        LDSM4(af[i][0], af[i][1], af[i][2], af[i][3], ad);
      }
#pragma unroll
      for (int j2 = 0; j2 < 4; j2++) {
        uint32_t bd = stB + b_row[j2] * 128 + ((((2 * ks + b_qc) ^ (b_row[j2] & 7))) << 4);
        uint32_t r0, r1, r2, r3;
        LDSM4(r0, r1, r2, r3, bd);
        bfr[2*j2][0] = r0; bfr[2*j2][1] = r1;
        bfr[2*j2+1][0] = r2; bfr[2*j2+1][1] = r3;
      }
#pragma unroll
      for (int i = 0; i < 2; i++)
#pragma unroll
        for (int j = 0; j < 8; j++)
          mma_f16(acc[i][j], af[i], bfr[j]);
    }
  }
#undef F16_LOAD
  if (epi == 0) {
#pragma unroll
    for (int i = 0; i < 2; i++) {
      int row0 = m0 + wm * 32 + i * 16 + group;
#pragma unroll
      for (int j = 0; j < 8; j++) {
        int col = n0 + wn * 64 + j * 8 + tg * 2;
        *(float2*)&C[(size_t)row0 * N + col]       = make_float2(acc[i][j][0], acc[i][j][1]);
        *(float2*)&C[(size_t)(row0 + 8) * N + col] = make_float2(acc[i][j][2], acc[i][j][3]);
      }
    }
  } else {
#pragma unroll
    for (int i = 0; i < 2; i++) {
      int row0 = m0 + wm * 32 + i * 16 + group;
      int ra = remap_row(row0), rb = remap_row(row0 + 8);
#pragma unroll
      for (int j = 0; j < 8; j++) {
        int col = n0 + wn * 64 + j * 8 + tg * 2;
        float b0 = bias[col], b1 = bias[col + 1];
        size_t oa = (size_t)ra * N + col, ob = (size_t)rb * N + col;
        float2 r0 = *(const float2*)&resid[oa];
        float2 r1 = *(const float2*)&resid[ob];
        *(float2*)&C[oa] = make_float2(geluf(acc[i][j][0] + b0) + r0.x,
                                       geluf(acc[i][j][1] + b1) + r0.y);
        *(float2*)&C[ob] = make_float2(geluf(acc[i][j][2] + b0) + r1.x,
                                       geluf(acc[i][j][3] + b1) + r1.y);
      }
    }
  }
}

// ================= GEMM TN (tf32, R8) =================
template<int MT, int WMW>
__global__ __launch_bounds__(256, 2) void gemm_tn(const float* __restrict__ At,
    const float* __restrict__ B, float* __restrict__ C, int M, int N, int K,
    int lda, int sA, int sC, int nsplit) {
  constexpr int WNW = 8 / WMW;
  constexpr int WNT = 128 / WNW;
  constexpr int JF  = WNT / 8;
  constexpr int JF2 = JF / 2;
  constexpr int AST = MT + 8;
  constexpr int STG = 32 * AST + 128 * 32;
  const int z = blockIdx.z;
  const int b = z / nsplit, s = z - b * nsplit;
  const int Kp = K / nsplit;
  At += (size_t)b * sA + (size_t)(s * Kp) * lda;
  C  += (size_t)z * sC;
  extern __shared__ float sm[];
  const uint32_t sbase = smem_u32(sm);
  const int tid = threadIdx.x;
  const int wid = tid >> 5, lane = tid & 31;
  const int wm = wid % WMW, wn = wid / WMW;
  const int group = lane >> 2, tg = lane & 3;
  const int m0 = blockIdx.y * MT, n0 = blockIdx.x * 128;
  const int lr = tid >> 3, lk = tid & 7;
  const int akk = tid >> 3, amc = tid & 7;
  const int KC = Kp / 32;

  int b_row[JF2];
#pragma unroll
  for (int j2 = 0; j2 < JF2; j2++)
    b_row[j2] = wn * WNT + j2 * 16 + (lane & 7) + ((lane & 16) ? 8 : 0);
  const int b_qc = (lane & 8) ? 1 : 0;

  float acc[2][JF][4] = {};

#define TN_LOAD(c) do { \
    int k0 = (c) * 32; \
    float* stA_ = sm + ((c) % 3) * STG; \
    float* stB_ = stA_ + 32 * AST; \
    _Pragma("unroll") \
    for (int pass = 0; pass < MT/32; ++pass) { \
      int mc = amc + pass * 8; \
      cp16(stA_ + akk * AST + mc * 4, &At[(size_t)(k0 + akk) * lda + m0 + mc * 4]); \
    } \
    _Pragma("unroll") \
    for (int pass = 0; pass < 4; ++pass) { \
      int r = lr + pass * 32; \
      int sc = (lk ^ (r & 7)) * 4; \
      cp16z(stB_ + r * 32 + sc, &B[(size_t)(n0 + r) * K + s * Kp + k0 + lk * 4], n0 + r < N); \
    } \
    CP_COMMIT(); \
  } while (0)

  TN_LOAD(0);
  if (KC > 1) TN_LOAD(1);
  for (int c = 0; c < KC; ++c) {
    if (c + 1 < KC) CP_WAIT1(); else CP_WAIT0();
    __syncthreads();
    if (c + 2 < KC) TN_LOAD(c + 2);
    float (*Asr)[AST] = (float(*)[AST])(sm + (c % 3) * STG);
    const uint32_t stB = sbase + ((c % 3) * STG + 32 * AST) * 4;
#pragma unroll
    for (int ks = 0; ks < 4; ++ks) {
      int kk = ks * 8;
      uint32_t af[2][4], bfr[JF][2];
#pragma unroll
      for (int i = 0; i < 2; i++) {
        int mr = wm * 32 + i * 16;
        af[i][0] = __float_as_uint(Asr[kk + tg    ][mr + group    ]);
        af[i][1] = __float_as_uint(Asr[kk + tg    ][mr + group + 8]);
        af[i][2] = __float_as_uint(Asr[kk + tg + 4][mr + group    ]);
        af[i][3] = __float_as_uint(Asr[kk + tg + 4][mr + group + 8]);
      }
#pragma unroll
      for (int j2 = 0; j2 < JF2; j2++) {
        uint32_t bd = stB + b_row[j2] * 128 + ((((2 * ks + b_qc) ^ (b_row[j2] & 7))) << 4);
        uint32_t r0, r1, r2, r3;
        LDSM4(r0, r1, r2, r3, bd);
        bfr[2*j2][0] = r0; bfr[2*j2][1] = r1;
        bfr[2*j2+1][0] = r2; bfr[2*j2+1][1] = r3;
      }
#pragma unroll
      for (int i = 0; i < 2; i++)
#pragma unroll
        for (int j = 0; j < JF; j++)
          mma_tf32(acc[i][j], af[i], bfr[j]);
    }
  }
#undef TN_LOAD
#pragma unroll
  for (int i = 0; i < 2; i++) {
    int row0 = m0 + wm * 32 + i * 16 + group;
#pragma unroll
    for (int j = 0; j < JF; j++) {
      int col = n0 + wn * WNT + j * 8 + tg * 2;
      if (col < N) {
        *(float2*)&C[(size_t)row0 * N + col]       = make_float2(acc[i][j][0], acc[i][j][1]);
        *(float2*)&C[(size_t)(row0 + 8) * N + col] = make_float2(acc[i][j][2], acc[i][j][3]);
      }
    }
  }
}
#define TN_SMEM3_128 (3*(32*136 + 128*32)*4)
#define TN_SMEM3_64  (3*(32*72  + 128*32)*4)

// ================= split-K reduce for dbc =================
__global__ void reduce_dbc() {
  int i = blockIdx.x * 256 + threadIdx.x;
  const int per = BATCH*SEQ*DBC_W/4;
  if (i >= per) return;
  const float4* p = (const float4*)g_dbcp;
  int b = i / (SEQ*DBC_W/4);
  int off = i - b * (SEQ*DBC_W/4);
  float4 r = make_float4(0.f,0.f,0.f,0.f);
#pragma unroll
  for (int s = 0; s < XSPLIT; s++) {
    float4 v = p[(size_t)(b*XSPLIT + s) * (SEQ*DBC_W/4) + off];
    r.x += v.x; r.y += v.y; r.z += v.z; r.w += v.w;
  }
  ((float4*)g_dbc)[i] = r;
}

// ================= delta via mma (R8) =================
__global__ __launch_bounds__(256) void delta_mma(const float* __restrict__ W,
    const float* __restrict__ dbc, const float* __restrict__ bias,
    float* __restrict__ outp) {
  __shared__ float As[128][36];
  __shared__ float Bs[64][36];
  const int b = blockIdx.z;
  const int tid = threadIdx.x;
  const int wid = tid >> 5, lane = tid & 31;
  const int wm = wid & 3, wn = wid >> 2;
  const int group = lane >> 2, tg = lane & 3;
  const int m0 = blockIdx.y * 128, n0 = blockIdx.x * 64;

  const float* Bb = dbc + (size_t)b * SEQ * DBC_W;
#pragma unroll
  for (int pass = 0; pass < 4; ++pass) {
    int i = tid + pass * 256;
    int r = i >> 3, q = i & 7;
    *(float4*)&As[r][q * 4] = *(const float4*)&W[(size_t)(m0 + r) * DTRANK + q * 4];
  }
#pragma unroll
  for (int pass = 0; pass < 2; ++pass) {
    int i = tid + pass * 256;
    int r = i >> 3, q = i & 7;
    *(float4*)&Bs[r][q * 4] = *(const float4*)&Bb[(size_t)(n0 + r) * DBC_W + q * 4];
  }
  __syncthreads();

  float acc[2][4][4] = {};
#pragma unroll
  for (int ks = 0; ks < 4; ++ks) {
    int kk = ks * 8;
    uint32_t af[2][4], bfr[4][2];
#pragma unroll
    for (int i = 0; i < 2; i++) {
      int mr = wm * 32 + i * 16;
      af[i][0] = __float_as_uint(As[mr + group    ][kk + tg    ]);
      af[i][1] = __float_as_uint(As[mr + group + 8][kk + tg    ]);
      af[i][2] = __float_as_uint(As[mr + group    ][kk + tg + 4]);
      af[i][3] = __float_as_uint(As[mr + group + 8][kk + tg + 4]);
    }
#pragma unroll
    for (int j = 0; j < 4; j++) {
      int nr = wn * 32 + j * 8;
      bfr[j][0] = __float_as_uint(Bs[nr + group][kk + tg    ]);
      bfr[j][1] = __float_as_uint(Bs[nr + group][kk + tg + 4]);
    }
#pragma unroll
    for (int i = 0; i < 2; i++)
#pragma unroll
      for (int j = 0; j < 4; j++)
        mma_tf32(acc[i][j], af[i], bfr[j]);
  }
  float* ob = outp + (size_t)b * DINNER * SEQ;
#pragma unroll
  for (int i = 0; i < 2; i++) {
    int d0 = m0 + wm * 32 + i * 16 + group;
    float ba = bias[d0], bb2 = bias[d0 + 8];
#pragma unroll
    for (int j = 0; j < 4; j++) {
      int t = n0 + wn * 32 + j * 8 + tg * 2;
      *(float2*)&ob[(size_t)d0 * SEQ + t] =
        make_float2(softplusf(acc[i][j][0] + ba), softplusf(acc[i][j][1] + ba));
      *(float2*)&ob[(size_t)(d0 + 8) * SEQ + t] =
        make_float2(softplusf(acc[i][j][2] + bb2), softplusf(acc[i][j][3] + bb2));
    }
  }
}

// ================= conv + silu + z-silu (R8) =================
__global__ void convz_kernel(const float* __restrict__ conv_w, const float* __restrict__ conv_b) {
  __shared__ float sx[67][33];
  __shared__ float sz[64][33];
  int b = blockIdx.z, t0 = blockIdx.x * 64, d0 = blockIdx.y * 32;
  int tid = threadIdx.y * 64 + threadIdx.x;
  for (int i = tid; i < 67*32; i += 256) {
    int r = i >> 5, c = i & 31;
    int t = t0 - 3 + r;
    sx[r][c] = (t >= 0) ? g_xz[(size_t)(b*SEQ + t)*2*DINNER + d0 + c] : 0.f;
  }
  for (int i = tid; i < 64*32; i += 256) {
    int r = i >> 5, c = i & 31;
    sz[r][c] = g_xz[(size_t)(b*SEQ + t0 + r)*2*DINNER + DINNER + d0 + c];
  }
  __syncthreads();
  int tx = threadIdx.x;
#pragma unroll
  for (int i = 0; i < 8; i++) {
    int dl = threadIdx.y * 8 + i;
    int d = d0 + dl;
    float w0 = conv_w[d*4+0], w1 = conv_w[d*4+1], w2 = conv_w[d*4+2], w3 = conv_w[d*4+3];
    float acc = conv_b[d];
    acc += sx[tx+0][dl]*w0 + sx[tx+1][dl]*w1 + sx[tx+2][dl]*w2 + sx[tx+3][dl]*w3;
    size_t o = (size_t)(b*DINNER + d)*SEQ + t0 + tx;
    g_ut[o] = siluf(acc);
    g_zt[o] = siluf(sz[tx][dl]);
  }
}

// ================= selective scan (R8) =================
__global__ void scan_kernel(const float* __restrict__ Dw, const float* __restrict__ A_log) {
  int warp = threadIdx.x >> 5, lane = threadIdx.x & 31;
  int g = blockIdx.x * 8 + warp;
  int b = g >> 10, d = g & 1023;
  __shared__ float sBC[32][64];
  __shared__ float sP[8][32][34];
  float An = -__expf(A_log[d*DSTATE + lane]);
  float Dd = Dw[d];
  float h = 0.f;
  const float* ut  = g_ut     + (size_t)(b*DINNER + d)*SEQ;
  const float* dtp = g_deltat + (size_t)(b*DINNER + d)*SEQ;
  const float* ztp = g_zt     + (size_t)(b*DINNER + d)*SEQ;
  float*       ytp = g_yt     + (size_t)(b*DINNER + d)*SEQ;

  for (int t0 = 0; t0 < SEQ; t0 += 32) {
    __syncthreads();
    for (int i = threadIdx.x; i < 32*64; i += 256) {
      int s = i >> 6, c = i & 63;
      sBC[s][c] = g_dbc[(size_t)(b*SEQ + t0 + s)*DBC_W + DSTATE + c];
    }
    __syncthreads();
    float du = ut[t0 + lane];
    float dd = dtp[t0 + lane];
    float sz = ztp[t0 + lane];
#pragma unroll 8
    for (int s = 0; s < 32; s++) {
      float delta_t = __shfl_sync(0xffffffffu, dd, s);
      float u_t     = __shfl_sync(0xffffffffu, du, s);
      float dA = __expf(delta_t * An);
      h = fmaf(dA, h, delta_t * u_t * sBC[s][lane]);
      sP[warp][s][lane] = h * sBC[s][32 + lane];
    }
    __syncwarp();
    float y = du * Dd;
#pragma unroll
    for (int i = 0; i < 32; i++) {
      int c = (lane + i) & 31;
      y += sP[warp][lane][c];
    }
    ytp[t0 + lane] = y * sz;
  }
}

// ================= layernorm -> fp16 output =================
__global__ void ln_kernel(const float* __restrict__ lnw, const float* __restrict__ lnb) {
  int row = blockIdx.x;
  const float* y = g_y2 + (size_t)row * DMODEL;
  __half*      o = g_ynh + (size_t)row * DMODEL;
  int tid = threadIdx.x;
  int lane = tid & 31, wid = tid >> 5;
  float v[4], s = 0.f, s2 = 0.f;
#pragma unroll
  for (int i = 0; i < 4; i++) {
    float x = y[tid + i*128];
    v[i] = x; s += x; s2 += x*x;
  }
#pragma unroll
  for (int off = 16; off >= 1; off >>= 1) {
    s  += __shfl_xor_sync(0xffffffffu, s, off);
    s2 += __shfl_xor_sync(0xffffffffu, s2, off);
  }
  __shared__ float sh[10];
  if (lane == 0) { sh[wid] = s; sh[4 + wid] = s2; }
  __syncthreads();
  if (tid == 0) {
    float ts = sh[0] + sh[1] + sh[2] + sh[3];
    float ts2 = sh[4] + sh[5] + sh[6] + sh[7];
    float mu = ts * (1.f/DMODEL);
    float var = ts2 * (1.f/DMODEL) - mu*mu;
    sh[8] = mu;
    sh[9] = rsqrtf(var + 1e-5f);
  }
  __syncthreads();
  float mu = sh[8], inv = sh[9];
#pragma unroll
  for (int i = 0; i < 4; i++) {
    int c = tid + i*128;
    o[c] = __float2half_rn((v[i] - mu) * inv * lnw[c] + lnb[c]);
  }
}

// ================= launch =================
extern "C" void kernel_launch(void* const* d_in, const int* in_sizes, int n_in,
                              void* d_out, int out_size) {
  const float* tokens     = (const float*)d_in[0];
  const float* in_proj_w  = (const float*)d_in[1];
  const float* conv_w     = (const float*)d_in[2];
  const float* conv_b     = (const float*)d_in[3];
  const float* x_proj_w   = (const float*)d_in[4];
  const float* dt_proj_w  = (const float*)d_in[5];
  const float* dt_proj_b  = (const float*)d_in[6];
  const float* A_log      = (const float*)d_in[7];
  const float* Dw         = (const float*)d_in[8];
  const float* out_proj_w = (const float*)d_in[9];
  const float* ln_w       = (const float*)d_in[10];
  const float* ln_b       = (const float*)d_in[11];
  const float* lin_w      = (const float*)d_in[12];
  const float* lin_b      = (const float*)d_in[13];
  float* out = (float*)d_out;

  float *p_xz, *p_ut, *p_dbcp, *p_dbc, *p_deltat, *p_yt, *p_y2;
  __half *p_ah, *p_bh, *p_ynh, *p_lwh;
  cudaGetSymbolAddress((void**)&p_xz,     g_xz);
  cudaGetSymbolAddress((void**)&p_ut,     g_ut);
  cudaGetSymbolAddress((void**)&p_dbcp,   g_dbcp);
  cudaGetSymbolAddress((void**)&p_dbc,    g_dbc);
  cudaGetSymbolAddress((void**)&p_deltat, g_deltat);
  cudaGetSymbolAddress((void**)&p_yt,     g_yt);
  cudaGetSymbolAddress((void**)&p_y2,     g_y2);
  cudaGetSymbolAddress((void**)&p_ah,     g_ah);
  cudaGetSymbolAddress((void**)&p_bh,     g_bh);
  cudaGetSymbolAddress((void**)&p_ynh,    g_ynh);
  cudaGetSymbolAddress((void**)&p_lwh,    g_lwh);

  cudaFuncSetAttribute(gemm_f16_nt, cudaFuncAttributeMaxDynamicSharedMemorySize, F16_SMEM3);
  cudaFuncSetAttribute(gemm_tn<128,4>, cudaFuncAttributeMaxDynamicSharedMemorySize, TN_SMEM3_128);
  cudaFuncSetAttribute(gemm_tn<64,2>,  cudaFuncAttributeMaxDynamicSharedMemorySize, TN_SMEM3_64);

  // 0. fp16 conversions
  tok2h<<<NROWS*DMODEL/4/256, 256>>>(tokens);
  w2h<<<2*DINNER*DMODEL/4/256, 256>>>(in_proj_w, p_bh);
  w2h<<<DMODEL*DMODEL/4/256, 256>>>(lin_w, p_lwh);
  // 1. xz = ah @ bh^T  (fp16)
  gemm_f16_nt<<<dim3(2*DINNER/128, NROWS/128), 256, F16_SMEM3>>>(
      p_ah, p_bh, p_xz, NROWS, 2*DINNER, DMODEL, 0, nullptr, nullptr);
  // 2. conv+silu -> ut ; silu(z) -> zt
  convz_kernel<<<dim3(SEQ/64, DINNER/32, BATCH), dim3(64,4)>>>(conv_w, conv_b);
  // 3. dbc partials (split-K=4)
  gemm_tn<128,4><<<dim3(1, SEQ/128, BATCH*XSPLIT), 256, TN_SMEM3_128>>>(
      p_ut, x_proj_w, p_dbcp, SEQ, DBC_W, DINNER, SEQ, DINNER*SEQ, SEQ*DBC_W, XSPLIT);
  // 3b. reduce partials
  reduce_dbc<<<(BATCH*SEQ*DBC_W/4 + 255)/256, 256>>>();
  // 4. delta
  delta_mma<<<dim3(SEQ/64, DINNER/128, BATCH), 256>>>(dt_proj_w, p_dbc, dt_proj_b, p_deltat);
  // 5. scan
  scan_kernel<<<NROWS/8, 256>>>(Dw, A_log);
  // 6. y2 = y @ out_proj_w^T
  gemm_tn<64,2><<<dim3(DMODEL/128, SEQ/64, BATCH), 256, TN_SMEM3_64>>>(
      p_yt, out_proj_w, p_y2, SEQ, DMODEL, DINNER, SEQ, DINNER*SEQ, SEQ*DMODEL, 1);
  // 7. layernorm -> fp16
  ln_kernel<<<NROWS, 128>>>(ln_w, ln_b);
  // 8. out = gelu(ynh @ lwh^T + lin_b) + residual  (fp16, fused epilogue)
  gemm_f16_nt<<<dim3(DMODEL/128, NROWS/128), 256, F16_SMEM3>>>(
      p_ynh, p_lwh, out, NROWS, DMODEL, DMODEL, 1, lin_b, tokens);
}

// round 16
// speedup vs baseline: 1.2619x; 1.0571x over previous
#include <cuda_runtime.h>
#include <cuda_fp16.h>
#include <cstdint>
#include <math.h>

#define BATCH  4
#define SEQ    1024
#define DMODEL 512
#define DINNER 1024
#define DSTATE 32
#define DTRANK 32
#define DBC_W  96
#define NROWS  (BATCH*SEQ)   // 4096
#define XSPLIT 4

// ================= scratch =================
__device__ float  g_xz    [BATCH*SEQ*2*DINNER];
__device__ float  g_ut    [BATCH*DINNER*SEQ];
__device__ float  g_zt    [BATCH*DINNER*SEQ];
__device__ float  g_dbcp  [XSPLIT*BATCH*SEQ*DBC_W];
__device__ float  g_dbc   [BATCH*SEQ*DBC_W];
__device__ float  g_deltat[BATCH*DINNER*SEQ];
__device__ __half g_yth   [BATCH*DINNER*SEQ];    // scan output, fp16 [b,d,t]
__device__ float  g_y2    [BATCH*SEQ*DMODEL];
__device__ __half g_ynh   [BATCH*SEQ*DMODEL];    // layernorm output, fp16
__device__ __half g_ah    [NROWS*DMODEL];        // permuted tokens, fp16
__device__ __half g_bh    [2*DINNER*DMODEL];     // in_proj_w, fp16
__device__ __half g_lwh   [DMODEL*DMODEL];       // lin_w, fp16
__device__ __half g_owh   [DMODEL*DINNER];       // out_proj_w, fp16

__device__ __forceinline__ int perm_src(int p) {
  int r = p >> 5, c = p & 31;
  if (r & 1) c = 31 - c;
  return (r << 5) | c;
}
__device__ __forceinline__ int remap_row(int m) {
  return (m & ~(SEQ - 1)) + perm_src(m & (SEQ - 1));
}
__device__ __forceinline__ float softplusf(float x) {
  return fmaxf(x, 0.f) + __logf(1.f + __expf(-fabsf(x)));
}
__device__ __forceinline__ float siluf(float x) {
  return __fdividef(x, 1.f + __expf(-x));
}
__device__ __forceinline__ float fast_erff(float x) {
  float ax = fabsf(x);
  float t = __frcp_rn(fmaf(0.3275911f, ax, 1.f));
  float p = t * fmaf(t, fmaf(t, fmaf(t, fmaf(t, 1.061405429f, -1.453152027f),
                     1.421413741f), -0.284496736f), 0.254829592f);
  float r = 1.f - p * __expf(-ax * ax);
  return copysignf(r, x);
}
__device__ __forceinline__ float geluf(float x) {
  return 0.5f * x * (1.f + fast_erff(x * 0.70710678118654752f));
}
__device__ __forceinline__ uint32_t smem_u32(const void* p) {
  uint32_t a;
  asm("{ .reg .u64 t; cvta.to.shared.u64 t, %1; cvt.u32.u64 %0, t; }" : "=r"(a) : "l"(p));
  return a;
}
__device__ __forceinline__ void cp16(void* dst, const void* src) {
  asm volatile("cp.async.cg.shared.global [%0], [%1], 16;"
               :: "r"(smem_u32(dst)), "l"(src));
}
__device__ __forceinline__ void cp16z(void* dst, const void* src, bool valid) {
  int sz = valid ? 16 : 0;
  asm volatile("cp.async.cg.shared.global [%0], [%1], 16, %2;"
               :: "r"(smem_u32(dst)), "l"(src), "r"(sz));
}
#define CP_COMMIT() asm volatile("cp.async.commit_group;" ::: "memory")
#define CP_WAIT1()  asm volatile("cp.async.wait_group 1;" ::: "memory")
#define CP_WAIT0()  asm volatile("cp.async.wait_group 0;" ::: "memory")

#define LDSM4(r0, r1, r2, r3, addr) \
  asm volatile("ldmatrix.sync.aligned.m8n8.x4.shared.b16 {%0,%1,%2,%3}, [%4];" \
    : "=r"(r0), "=r"(r1), "=r"(r2), "=r"(r3) : "r"(addr))
#define LDSM4T(r0, r1, r2, r3, addr) \
  asm volatile("ldmatrix.sync.aligned.m8n8.x4.trans.shared.b16 {%0,%1,%2,%3}, [%4];" \
    : "=r"(r0), "=r"(r1), "=r"(r2), "=r"(r3) : "r"(addr))

__device__ __forceinline__ void mma_tf32(float* c, const uint32_t* a, const uint32_t* b) {
  asm volatile(
    "mma.sync.aligned.m16n8k8.row.col.f32.tf32.tf32.f32 "
    "{%0,%1,%2,%3}, {%4,%5,%6,%7}, {%8,%9}, {%0,%1,%2,%3};"
    : "+f"(c[0]), "+f"(c[1]), "+f"(c[2]), "+f"(c[3])
    : "r"(a[0]), "r"(a[1]), "r"(a[2]), "r"(a[3]), "r"(b[0]), "r"(b[1]));
}
__device__ __forceinline__ void mma_f16(float* c, const uint32_t* a, const uint32_t* b) {
  asm volatile(
    "mma.sync.aligned.m16n8k16.row.col.f32.f16.f16.f32 "
    "{%0,%1,%2,%3}, {%4,%5,%6,%7}, {%8,%9}, {%0,%1,%2,%3};"
    : "+f"(c[0]), "+f"(c[1]), "+f"(c[2]), "+f"(c[3])
    : "r"(a[0]), "r"(a[1]), "r"(a[2]), "r"(a[3]), "r"(b[0]), "r"(b[1]));
}

// ================= fp32->fp16 converters =================
__global__ void tok2h(const float* __restrict__ tokens) {
  int i = blockIdx.x * 256 + threadIdx.x;
  int row = i >> 7, c4 = (i & 127) * 4;
  float4 v = *(const float4*)&tokens[(size_t)remap_row(row) * DMODEL + c4];
  __half2* dst = (__half2*)&g_ah[(size_t)row * DMODEL + c4];
  dst[0] = __floats2half2_rn(v.x, v.y);
  dst[1] = __floats2half2_rn(v.z, v.w);
}
__global__ void w2h(const float* __restrict__ w, __half* __restrict__ o) {
  int i = blockIdx.x * 256 + threadIdx.x;
  float4 v = *(const float4*)&w[(size_t)i * 4];
  __half2* dst = (__half2*)&o[(size_t)i * 4];
  dst[0] = __floats2half2_rn(v.x, v.y);
  dst[1] = __floats2half2_rn(v.z, v.w);
}

// ================= fp16 GEMM NT ==================
#define F16_STAGE_B (2*128*128)
#define F16_SMEM3   (3*F16_STAGE_B)        // 98304 B
__global__ __launch_bounds__(256, 2) void gemm_f16_nt(const __half* __restrict__ A,
    const __half* __restrict__ B, float* __restrict__ C, int M, int N, int K,
    int epi, const float* __restrict__ bias, const float* __restrict__ resid) {
  extern __shared__ char smc[];
  const uint32_t sbase = smem_u32(smc);
  const int tid = threadIdx.x;
  const int wid = tid >> 5, lane = tid & 31;
  const int wm = wid & 3, wn = wid >> 2;
  const int group = lane >> 2, tg = lane & 3;
  const int m0 = blockIdx.y * 128, n0 = blockIdx.x * 128;
  const int lr = tid >> 3, lk = tid & 7;
  const int KC = K / 64;

  int a_row[2], b_row[4];
#pragma unroll
  for (int i = 0; i < 2; i++)
    a_row[i] = wm * 32 + i * 16 + (lane & 7) + ((lane & 8) ? 8 : 0);
#pragma unroll
  for (int j2 = 0; j2 < 4; j2++)
    b_row[j2] = wn * 64 + j2 * 16 + (lane & 7) + ((lane & 16) ? 8 : 0);
  const int a_qc = (lane & 16) ? 1 : 0;
  const int b_qc = (lane & 8) ? 1 : 0;

  float acc[2][8][4] = {};

#define F16_LOAD(c) do { \
    int k0 = (c) * 64; \
    char* st = smc + ((c) % 3) * F16_STAGE_B; \
    _Pragma("unroll") \
    for (int pass = 0; pass < 4; ++pass) { \
      int r = lr + pass * 32; \
      int sc = (lk ^ (r & 7)) * 16; \
      cp16(st + r * 128 + sc, &A[(size_t)(m0 + r) * K + k0 + lk * 8]); \
      cp16(st + 128 * 128 + r * 128 + sc, &B[(size_t)(n0 + r) * K + k0 + lk * 8]); \
    } \
    CP_COMMIT(); \
  } while (0)

  F16_LOAD(0);
  if (KC > 1) F16_LOAD(1);
  for (int c = 0; c < KC; ++c) {
    if (c + 1 < KC) CP_WAIT1(); else CP_WAIT0();
    __syncthreads();
    if (c + 2 < KC) F16_LOAD(c + 2);
    const uint32_t stA = sbase + (c % 3) * F16_STAGE_B;
    const uint32_t stB = stA + 128 * 128;
#pragma unroll
    for (int ks = 0; ks < 4; ++ks) {
      uint32_t af[2][4], bfr[8][2];
#pragma unroll
      for (int i = 0; i < 2; i++) {
        uint32_t ad = stA + a_row[i] * 128 + ((((2 * ks + a_qc) ^ (a_row[i] & 7))) << 4);
        LDSM4(af[i][0], af[i][1], af[i][2], af[i][3], ad);
      }
#pragma unroll
      for (int j2 = 0; j2 < 4; j2++) {
        uint32_t bd = stB + b_row[j2] * 128 + ((((2 * ks + b_qc) ^ (b_row[j2] & 7))) << 4);
        uint32_t r0, r1, r2, r3;
        LDSM4(r0, r1, r2, r3, bd);
        bfr[2*j2][0] = r0; bfr[2*j2][1] = r1;
        bfr[2*j2+1][0] = r2; bfr[2*j2+1][1] = r3;
      }
#pragma unroll
      for (int i = 0; i < 2; i++)
#pragma unroll
        for (int j = 0; j < 8; j++)
          mma_f16(acc[i][j], af[i], bfr[j]);
    }
  }
#undef F16_LOAD
  if (epi == 0) {
#pragma unroll
    for (int i = 0; i < 2; i++) {
      int row0 = m0 + wm * 32 + i * 16 + group;
#pragma unroll
      for (int j = 0; j < 8; j++) {
        int col = n0 + wn * 64 + j * 8 + tg * 2;
        *(float2*)&C[(size_t)row0 * N + col]       = make_float2(acc[i][j][0], acc[i][j][1]);
        *(float2*)&C[(size_t)(row0 + 8) * N + col] = make_float2(acc[i][j][2], acc[i][j][3]);
      }
    }
  } else {
#pragma unroll
    for (int i = 0; i < 2; i++) {
      int row0 = m0 + wm * 32 + i * 16 + group;
      int ra = remap_row(row0), rb = remap_row(row0 + 8);
#pragma unroll
      for (int j = 0; j < 8; j++) {
        int col = n0 + wn * 64 + j * 8 + tg * 2;
        float b0 = bias[col], b1 = bias[col + 1];
        size_t oa = (size_t)ra * N + col, ob = (size_t)rb * N + col;
        float2 r0 = *(const float2*)&resid[oa];
        float2 r1 = *(const float2*)&resid[ob];
        *(float2*)&C[oa] = make_float2(geluf(acc[i][j][0] + b0) + r0.x,
                                       geluf(acc[i][j][1] + b1) + r0.y);
        *(float2*)&C[ob] = make_float2(geluf(acc[i][j][2] + b0) + r1.x,
                                       geluf(acc[i][j][3] + b1) + r1.y);
      }
    }
  }
}

// ================= fp16 GEMM TN (A k-major via ldmatrix.trans) ==================
// C[M,N] = At^T @ B^T ; At [K, lda] fp16 (m contiguous), B [N,K] fp16. MT=64.
// A stage: 64 k-rows x 64 m fp16 = 128 B rows, XOR swizzle. batched via z.
#define F16TN_A_B (64*128)
#define F16TN_STG (F16TN_A_B + 128*128)     // 24576 B per stage
#define F16TN_SMEM3 (3*F16TN_STG)           // 73728 B
__global__ __launch_bounds__(256, 2) void gemm_f16_tn(const __half* __restrict__ At,
    const __half* __restrict__ B, float* __restrict__ C, int M, int N, int K,
    int lda, int sA, int sC) {
  At += (size_t)blockIdx.z * sA;
  C  += (size_t)blockIdx.z * sC;
  extern __shared__ char smc[];
  const uint32_t sbase = smem_u32(smc);
  const int tid = threadIdx.x;
  const int wid = tid >> 5, lane = tid & 31;
  const int wm = wid & 1, wn = wid >> 1;     // 2 m-warps x 4 n-warps, warp tile 32x32
  const int group = lane >> 2, tg = lane & 3;
  const int m0 = blockIdx.y * 64, n0 = blockIdx.x * 128;
  const int lr = tid >> 3, lk = tid & 7;
  const int KC = K / 64;

  // A trans-ldmatrix geometry: kr = k-row within 16-step, mchunk = 16B col chunk
  const int a_kr = (lane & 7) + ((lane & 16) ? 8 : 0);
  int a_mch[2];
#pragma unroll
  for (int i = 0; i < 2; i++)
    a_mch[i] = wm * 4 + i * 2 + ((lane & 8) ? 1 : 0);
  int b_row[2];
#pragma unroll
  for (int j2 = 0; j2 < 2; j2++)
    b_row[j2] = wn * 32 + j2 * 16 + (lane & 7) + ((lane & 16) ? 8 : 0);
  const int b_qc = (lane & 8) ? 1 : 0;

  float acc[2][4][4] = {};

#define F16TN_LOAD(c) do { \
    int k0 = (c) * 64; \
    char* stA_ = smc + ((c) % 3) * F16TN_STG; \
    char* stB_ = stA_ + F16TN_A_B; \
    { /* A: 64 rows x 8 chunks = 512 cp16 / 256 thr = 2 passes */ \
      _Pragma("unroll") \
      for (int pass = 0; pass < 2; ++pass) { \
        int r = lr + pass * 32; \
        int sc = (lk ^ (r & 7)) * 16; \
        cp16(stA_ + r * 128 + sc, &At[(size_t)(k0 + r) * lda + m0 + lk * 8]); \
      } \
    } \
    _Pragma("unroll") \
    for (int pass = 0; pass < 4; ++pass) { \
      int r = lr + pass * 32; \
      int sc = (lk ^ (r & 7)) * 16; \
      cp16(stB_ + r * 128 + sc, &B[(size_t)(n0 + r) * K + k0 + lk * 8]); \
    } \
    CP_COMMIT(); \
  } while (0)

  F16TN_LOAD(0);
  if (KC > 1) F16TN_LOAD(1);
  for (int c = 0; c < KC; ++c) {
    if (c + 1 < KC) CP_WAIT1(); else CP_WAIT0();
    __syncthreads();
    if (c + 2 < KC) F16TN_LOAD(c + 2);
    const uint32_t stA = sbase + (c % 3) * F16TN_STG;
    const uint32_t stB = stA + F16TN_A_B;
#pragma unroll
    for (int ks = 0; ks < 4; ++ks) {
      int krow = ks * 16 + a_kr;
      uint32_t af[2][4], bfr[4][2];
#pragma unroll
      for (int i = 0; i < 2; i++) {
        uint32_t ad = stA + krow * 128 + (((a_mch[i] ^ (krow & 7))) << 4);
        LDSM4T(af[i][0], af[i][1], af[i][2], af[i][3], ad);
      }
#pragma unroll
      for (int j2 = 0; j2 < 2; j2++) {
        uint32_t bd = stB + b_row[j2] * 128 + ((((2 * ks + b_qc) ^ (b_row[j2] & 7))) << 4);
        uint32_t r0, r1, r2, r3;
        LDSM4(r0, r1, r2, r3, bd);
        bfr[2*j2][0] = r0; bfr[2*j2][1] = r1;
        bfr[2*j2+1][0] = r2; bfr[2*j2+1][1] = r3;
      }
#pragma unroll
      for (int i = 0; i < 2; i++)
#pragma unroll
        for (int j = 0; j < 4; j++)
          mma_f16(acc[i][j], af[i], bfr[j]);
    }
  }
#undef F16TN_LOAD
#pragma unroll
  for (int i = 0; i < 2; i++) {
    int row0 = m0 + wm * 32 + i * 16 + group;
#pragma unroll
    for (int j = 0; j < 4; j++) {
      int col = n0 + wn * 32 + j * 8 + tg * 2;
      *(float2*)&C[(size_t)row0 * N + col]       = make_float2(acc[i][j][0], acc[i][j][1]);
      *(float2*)&C[(size_t)(row0 + 8) * N + col] = make_float2(acc[i][j][2], acc[i][j][3]);
    }
  }
}

// ================= GEMM TN (tf32, R8) — x_proj only =================
template<int MT, int WMW>
__global__ __launch_bounds__(256, 2) void gemm_tn(const float* __restrict__ At,
    const float* __restrict__ B, float* __restrict__ C, int M, int N, int K,
    int lda, int sA, int sC, int nsplit) {
  constexpr int WNW = 8 / WMW;
  constexpr int WNT = 128 / WNW;
  constexpr int JF  = WNT / 8;
  constexpr int JF2 = JF / 2;
  constexpr int AST = MT + 8;
  constexpr int STG = 32 * AST + 128 * 32;
  const int z = blockIdx.z;
  const int b = z / nsplit, s = z - b * nsplit;
  const int Kp = K / nsplit;
  At += (size_t)b * sA + (size_t)(s * Kp) * lda;
  C  += (size_t)z * sC;
  extern __shared__ float sm[];
  const uint32_t sbase = smem_u32(sm);
  const int tid = threadIdx.x;
  const int wid = tid >> 5, lane = tid & 31;
  const int wm = wid % WMW, wn = wid / WMW;
  const int group = lane >> 2, tg = lane & 3;
  const int m0 = blockIdx.y * MT, n0 = blockIdx.x * 128;
  const int lr = tid >> 3, lk = tid & 7;
  const int akk = tid >> 3, amc = tid & 7;
  const int KC = Kp / 32;

  int b_row[JF2];
#pragma unroll
  for (int j2 = 0; j2 < JF2; j2++)
    b_row[j2] = wn * WNT + j2 * 16 + (lane & 7) + ((lane & 16) ? 8 : 0);
  const int b_qc = (lane & 8) ? 1 : 0;

  float acc[2][JF][4] = {};

#define TN_LOAD(c) do { \
    int k0 = (c) * 32; \
    float* stA_ = sm + ((c) % 3) * STG; \
    float* stB_ = stA_ + 32 * AST; \
    _Pragma("unroll") \
    for (int pass = 0; pass < MT/32; ++pass) { \
      int mc = amc + pass * 8; \
      cp16(stA_ + akk * AST + mc * 4, &At[(size_t)(k0 + akk) * lda + m0 + mc * 4]); \
    } \
    _Pragma("unroll") \
    for (int pass = 0; pass < 4; ++pass) { \
      int r = lr + pass * 32; \
      int sc = (lk ^ (r & 7)) * 4; \
      cp16z(stB_ + r * 32 + sc, &B[(size_t)(n0 + r) * K + s * Kp + k0 + lk * 4], n0 + r < N); \
    } \
    CP_COMMIT(); \
  } while (0)

  TN_LOAD(0);
  if (KC > 1) TN_LOAD(1);
  for (int c = 0; c < KC; ++c) {
    if (c + 1 < KC) CP_WAIT1(); else CP_WAIT0();
    __syncthreads();
    if (c + 2 < KC) TN_LOAD(c + 2);
    float (*Asr)[AST] = (float(*)[AST])(sm + (c % 3) * STG);
    const uint32_t stB = sbase + ((c % 3) * STG + 32 * AST) * 4;
#pragma unroll
    for (int ks = 0; ks < 4; ++ks) {
      int kk = ks * 8;
      uint32_t af[2][4], bfr[JF][2];
#pragma unroll
      for (int i = 0; i < 2; i++) {
        int mr = wm * 32 + i * 16;
        af[i][0] = __float_as_uint(Asr[kk + tg    ][mr + group    ]);
        af[i][1] = __float_as_uint(Asr[kk + tg    ][mr + group + 8]);
        af[i][2] = __float_as_uint(Asr[kk + tg + 4][mr + group    ]);
        af[i][3] = __float_as_uint(Asr[kk + tg + 4][mr + group + 8]);
      }
#pragma unroll
      for (int j2 = 0; j2 < JF2; j2++) {
        uint32_t bd = stB + b_row[j2] * 128 + ((((2 * ks + b_qc) ^ (b_row[j2] & 7))) << 4);
        uint32_t r0, r1, r2, r3;
        LDSM4(r0, r1, r2, r3, bd);
        bfr[2*j2][0] = r0; bfr[2*j2][1] = r1;
        bfr[2*j2+1][0] = r2; bfr[2*j2+1][1] = r3;
      }
#pragma unroll
      for (int i = 0; i < 2; i++)
#pragma unroll
        for (int j = 0; j < JF; j++)
          mma_tf32(acc[i][j], af[i], bfr[j]);
    }
  }
#undef TN_LOAD
#pragma unroll
  for (int i = 0; i < 2; i++) {
    int row0 = m0 + wm * 32 + i * 16 + group;
#pragma unroll
    for (int j = 0; j < JF; j++) {
      int col = n0 + wn * WNT + j * 8 + tg * 2;
      if (col < N) {
        *(float2*)&C[(size_t)row0 * N + col]       = make_float2(acc[i][j][0], acc[i][j][1]);
        *(float2*)&C[(size_t)(row0 + 8) * N + col] = make_float2(acc[i][j][2], acc[i][j][3]);
      }
    }
  }
}
#define TN_SMEM3_128 (3*(32*136 + 128*32)*4)

// ================= split-K reduce for dbc =================
__global__ void reduce_dbc() {
  int i = blockIdx.x * 256 + threadIdx.x;
  const int per = BATCH*SEQ*DBC_W/4;
  if (i >= per) return;
  const float4* p = (const float4*)g_dbcp;
  int b = i / (SEQ*DBC_W/4);
  int off = i - b * (SEQ*DBC_W/4);
  float4 r = make_float4(0.f,0.f,0.f,0.f);
#pragma unroll
  for (int s = 0; s < XSPLIT; s++) {
    float4 v = p[(size_t)(b*XSPLIT + s) * (SEQ*DBC_W/4) + off];
    r.x += v.x; r.y += v.y; r.z += v.z; r.w += v.w;
  }
  ((float4*)g_dbc)[i] = r;
}

// ================= delta via mma (R8) =================
__global__ __launch_bounds__(256) void delta_mma(const float* __restrict__ W,
    const float* __restrict__ dbc, const float* __restrict__ bias,
    float* __restrict__ outp) {
  __shared__ float As[128][36];
  __shared__ float Bs[64][36];
  const int b = blockIdx.z;
  const int tid = threadIdx.x;
  const int wid = tid >> 5, lane = tid & 31;
  const int wm = wid & 3, wn = wid >> 2;
  const int group = lane >> 2, tg = lane & 3;
  const int m0 = blockIdx.y * 128, n0 = blockIdx.x * 64;

  const float* Bb = dbc + (size_t)b * SEQ * DBC_W;
#pragma unroll
  for (int pass = 0; pass < 4; ++pass) {
    int i = tid + pass * 256;
    int r = i >> 3, q = i & 7;
    *(float4*)&As[r][q * 4] = *(const float4*)&W[(size_t)(m0 + r) * DTRANK + q * 4];
  }
#pragma unroll
  for (int pass = 0; pass < 2; ++pass) {
    int i = tid + pass * 256;
    int r = i >> 3, q = i & 7;
    *(float4*)&Bs[r][q * 4] = *(const float4*)&Bb[(size_t)(n0 + r) * DBC_W + q * 4];
  }
  __syncthreads();

  float acc[2][4][4] = {};
#pragma unroll
  for (int ks = 0; ks < 4; ++ks) {
    int kk = ks * 8;
    uint32_t af[2][4], bfr[4][2];
#pragma unroll
    for (int i = 0; i < 2; i++) {
      int mr = wm * 32 + i * 16;
      af[i][0] = __float_as_uint(As[mr + group    ][kk + tg    ]);
      af[i][1] = __float_as_uint(As[mr + group + 8][kk + tg    ]);
      af[i][2] = __float_as_uint(As[mr + group    ][kk + tg + 4]);
      af[i][3] = __float_as_uint(As[mr + group + 8][kk + tg + 4]);
    }
#pragma unroll
    for (int j = 0; j < 4; j++) {
      int nr = wn * 32 + j * 8;
      bfr[j][0] = __float_as_uint(Bs[nr + group][kk + tg    ]);
      bfr[j][1] = __float_as_uint(Bs[nr + group][kk + tg + 4]);
    }
#pragma unroll
    for (int i = 0; i < 2; i++)
#pragma unroll
      for (int j = 0; j < 4; j++)
        mma_tf32(acc[i][j], af[i], bfr[j]);
  }
  float* ob = outp + (size_t)b * DINNER * SEQ;
#pragma unroll
  for (int i = 0; i < 2; i++) {
    int d0 = m0 + wm * 32 + i * 16 + group;
    float ba = bias[d0], bb2 = bias[d0 + 8];
#pragma unroll
    for (int j = 0; j < 4; j++) {
      int t = n0 + wn * 32 + j * 8 + tg * 2;
      *(float2*)&ob[(size_t)d0 * SEQ + t] =
        make_float2(softplusf(acc[i][j][0] + ba), softplusf(acc[i][j][1] + ba));
      *(float2*)&ob[(size_t)(d0 + 8) * SEQ + t] =
        make_float2(softplusf(acc[i][j][2] + bb2), softplusf(acc[i][j][3] + bb2));
    }
  }
}

// ================= conv + silu + z-silu (R8) =================
__global__ void convz_kernel(const float* __restrict__ conv_w, const float* __restrict__ conv_b) {
  __shared__ float sx[67][33];
  __shared__ float sz[64][33];
  int b = blockIdx.z, t0 = blockIdx.x * 64, d0 = blockIdx.y * 32;
  int tid = threadIdx.y * 64 + threadIdx.x;
  for (int i = tid; i < 67*32; i += 256) {
    int r = i >> 5, c = i & 31;
    int t = t0 - 3 + r;
    sx[r][c] = (t >= 0) ? g_xz[(size_t)(b*SEQ + t)*2*DINNER + d0 + c] : 0.f;
  }
  for (int i = tid; i < 64*32; i += 256) {
    int r = i >> 5, c = i & 31;
    sz[r][c] = g_xz[(size_t)(b*SEQ + t0 + r)*2*DINNER + DINNER + d0 + c];
  }
  __syncthreads();
  int tx = threadIdx.x;
#pragma unroll
  for (int i = 0; i < 8; i++) {
    int dl = threadIdx.y * 8 + i;
    int d = d0 + dl;
    float w0 = conv_w[d*4+0], w1 = conv_w[d*4+1], w2 = conv_w[d*4+2], w3 = conv_w[d*4+3];
    float acc = conv_b[d];
    acc += sx[tx+0][dl]*w0 + sx[tx+1][dl]*w1 + sx[tx+2][dl]*w2 + sx[tx+3][dl]*w3;
    size_t o = (size_t)(b*DINNER + d)*SEQ + t0 + tx;
    g_ut[o] = siluf(acc);
    g_zt[o] = siluf(sz[tx][dl]);
  }
}

// ================= selective scan (R8, fp16 yt output) =================
__global__ void scan_kernel(const float* __restrict__ Dw, const float* __restrict__ A_log) {
  int warp = threadIdx.x >> 5, lane = threadIdx.x & 31;
  int g = blockIdx.x * 8 + warp;
  int b = g >> 10, d = g & 1023;
  __shared__ float sBC[32][64];
  __shared__ float sP[8][32][34];
  float An = -__expf(A_log[d*DSTATE + lane]);
  float Dd = Dw[d];
  float h = 0.f;
  const float* ut  = g_ut     + (size_t)(b*DINNER + d)*SEQ;
  const float* dtp = g_deltat + (size_t)(b*DINNER + d)*SEQ;
  const float* ztp = g_zt     + (size_t)(b*DINNER + d)*SEQ;
  __half*      ytp = g_yth    + (size_t)(b*DINNER + d)*SEQ;

  for (int t0 = 0; t0 < SEQ; t0 += 32) {
    __syncthreads();
    for (int i = threadIdx.x; i < 32*64; i += 256) {
      int s = i >> 6, c = i & 63;
      sBC[s][c] = g_dbc[(size_t)(b*SEQ + t0 + s)*DBC_W + DSTATE + c];
    }
    __syncthreads();
    float du = ut[t0 + lane];
    float dd = dtp[t0 + lane];
    float sz = ztp[t0 + lane];
#pragma unroll 8
    for (int s = 0; s < 32; s++) {
      float delta_t = __shfl_sync(0xffffffffu, dd, s);
      float u_t     = __shfl_sync(0xffffffffu, du, s);
      float dA = __expf(delta_t * An);
      h = fmaf(dA, h, delta_t * u_t * sBC[s][lane]);
      sP[warp][s][lane] = h * sBC[s][32 + lane];
    }
    __syncwarp();
    float y = du * Dd;
#pragma unroll
    for (int i = 0; i < 32; i++) {
      int c = (lane + i) & 31;
      y += sP[warp][lane][c];
    }
    ytp[t0 + lane] = __float2half_rn(y * sz);
  }
}

// ================= layernorm -> fp16 output =================
__global__ void ln_kernel(const float* __restrict__ lnw, const float* __restrict__ lnb) {
  int row = blockIdx.x;
  const float* y = g_y2 + (size_t)row * DMODEL;
  __half*      o = g_ynh + (size_t)row * DMODEL;
  int tid = threadIdx.x;
  int lane = tid & 31, wid = tid >> 5;
  float v[4], s = 0.f, s2 = 0.f;
#pragma unroll
  for (int i = 0; i < 4; i++) {
    float x = y[tid + i*128];
    v[i] = x; s += x; s2 += x*x;
  }
#pragma unroll
  for (int off = 16; off >= 1; off >>= 1) {
    s  += __shfl_xor_sync(0xffffffffu, s, off);
    s2 += __shfl_xor_sync(0xffffffffu, s2, off);
  }
  __shared__ float sh[10];
  if (lane == 0) { sh[wid] = s; sh[4 + wid] = s2; }
  __syncthreads();
  if (tid == 0) {
    float ts = sh[0] + sh[1] + sh[2] + sh[3];
    float ts2 = sh[4] + sh[5] + sh[6] + sh[7];
    float mu = ts * (1.f/DMODEL);
    float var = ts2 * (1.f/DMODEL) - mu*mu;
    sh[8] = mu;
    sh[9] = rsqrtf(var + 1e-5f);
  }
  __syncthreads();
  float mu = sh[8], inv = sh[9];
#pragma unroll
  for (int i = 0; i < 4; i++) {
    int c = tid + i*128;
    o[c] = __float2half_rn((v[i] - mu) * inv * lnw[c] + lnb[c]);
  }
}

// ================= launch =================
extern "C" void kernel_launch(void* const* d_in, const int* in_sizes, int n_in,
                              void* d_out, int out_size) {
  const float* tokens     = (const float*)d_in[0];
  const float* in_proj_w  = (const float*)d_in[1];
  const float* conv_w     = (const float*)d_in[2];
  const float* conv_b     = (const float*)d_in[3];
  const float* x_proj_w   = (const float*)d_in[4];
  const float* dt_proj_w  = (const float*)d_in[5];
  const float* dt_proj_b  = (const float*)d_in[6];
  const float* A_log      = (const float*)d_in[7];
  const float* Dw         = (const float*)d_in[8];
  const float* out_proj_w = (const float*)d_in[9];
  const float* ln_w       = (const float*)d_in[10];
  const float* ln_b       = (const float*)d_in[11];
  const float* lin_w      = (const float*)d_in[12];
  const float* lin_b      = (const float*)d_in[13];
  float* out = (float*)d_out;

  float *p_xz, *p_ut, *p_dbcp, *p_dbc, *p_deltat, *p_y2;
  __half *p_ah, *p_bh, *p_ynh, *p_lwh, *p_yth, *p_owh;
  cudaGetSymbolAddress((void**)&p_xz,     g_xz);
  cudaGetSymbolAddress((void**)&p_ut,     g_ut);
  cudaGetSymbolAddress((void**)&p_dbcp,   g_dbcp);
  cudaGetSymbolAddress((void**)&p_dbc,    g_dbc);
  cudaGetSymbolAddress((void**)&p_deltat, g_deltat);
  cudaGetSymbolAddress((void**)&p_y2,     g_y2);
  cudaGetSymbolAddress((void**)&p_ah,     g_ah);
  cudaGetSymbolAddress((void**)&p_bh,     g_bh);
  cudaGetSymbolAddress((void**)&p_ynh,    g_ynh);
  cudaGetSymbolAddress((void**)&p_lwh,    g_lwh);
  cudaGetSymbolAddress((void**)&p_yth,    g_yth);
  cudaGetSymbolAddress((void**)&p_owh,    g_owh);

  cudaFuncSetAttribute(gemm_f16_nt, cudaFuncAttributeMaxDynamicSharedMemorySize, F16_SMEM3);
  cudaFuncSetAttribute(gemm_f16_tn, cudaFuncAttributeMaxDynamicSharedMemorySize, F16TN_SMEM3);
  cudaFuncSetAttribute(gemm_tn<128,4>, cudaFuncAttributeMaxDynamicSharedMemorySize, TN_SMEM3_128);

  // 0. fp16 conversions
  tok2h<<<NROWS*DMODEL/4/256, 256>>>(tokens);
  w2h<<<2*DINNER*DMODEL/4/256, 256>>>(in_proj_w, p_bh);
  w2h<<<DMODEL*DMODEL/4/256, 256>>>(lin_w, p_lwh);
  w2h<<<DMODEL*DINNER/4/256, 256>>>(out_proj_w, p_owh);
  // 1. xz = ah @ bh^T  (fp16)
  gemm_f16_nt<<<dim3(2*DINNER/128, NROWS/128), 256, F16_SMEM3>>>(
      p_ah, p_bh, p_xz, NROWS, 2*DINNER, DMODEL, 0, nullptr, nullptr);
  // 2. conv+silu -> ut ; silu(z) -> zt
  convz_kernel<<<dim3(SEQ/64, DINNER/32, BATCH), dim3(64,4)>>>(conv_w, conv_b);
  // 3. dbc partials (split-K=4, tf32)
  gemm_tn<128,4><<<dim3(1, SEQ/128, BATCH*XSPLIT), 256, TN_SMEM3_128>>>(
      p_ut, x_proj_w, p_dbcp, SEQ, DBC_W, DINNER, SEQ, DINNER*SEQ, SEQ*DBC_W, XSPLIT);
  // 3b. reduce partials
  reduce_dbc<<<(BATCH*SEQ*DBC_W/4 + 255)/256, 256>>>();
  // 4. delta
  delta_mma<<<dim3(SEQ/64, DINNER/128, BATCH), 256>>>(dt_proj_w, p_dbc, dt_proj_b, p_deltat);
  // 5. scan -> yth (fp16)
  scan_kernel<<<NROWS/8, 256>>>(Dw, A_log);
  // 6. y2 = yth^T @ out_proj_w^T  (fp16 TN, ldmatrix.trans A)
  gemm_f16_tn<<<dim3(DMODEL/128, SEQ/64, BATCH), 256, F16TN_SMEM3>>>(
      p_yth, p_owh, p_y2, SEQ, DMODEL, DINNER, SEQ, DINNER*SEQ, SEQ*DMODEL);
  // 7. layernorm -> fp16
  ln_kernel<<<NROWS, 128>>>(ln_w, ln_b);
  // 8. out = gelu(ynh @ lwh^T + lin_b) + residual  (fp16, fused epilogue)
  gemm_f16_nt<<<dim3(DMODEL/128, NROWS/128), 256, F16_SMEM3>>>(
      p_ynh, p_lwh, out, NROWS, DMODEL, DMODEL, 1, lin_b, tokens);
}